// round 3
// baseline (speedup 1.0000x reference)
#include <cuda_runtime.h>
#include <math.h>
#include <stddef.h>

#define BATCH  64
#define NTOK   4096
#define DIM    256
#define SDIM   256
#define KSLOT  8
#define HID    512
#define EPSA   1e-8f
#define LNEPS  1e-5f
#define NROWS  (BATCH*NTOK)       /* 262144 */
#define NCHUNK 8

/* ------------- scratch (device globals; no allocation allowed) ---------- */
__device__ float g_mean[NROWS];
__device__ float g_rstd[NROWS];
__device__ float g_k[NROWS*SDIM];                 /* 256 MB */
__device__ float g_v[NROWS*SDIM];                 /* 256 MB */
__device__ float g_attn[NROWS*KSLOT];             /* 8 MB   */
__device__ float g_slots[BATCH*KSLOT*SDIM];
__device__ float g_q[BATCH*KSLOT*SDIM];
__device__ float g_upd[BATCH*KSLOT*SDIM];
__device__ float g_updpart[NCHUNK*BATCH*KSLOT*SDIM];
__device__ float g_cspart[BATCH*NCHUNK*KSLOT];

__device__ __forceinline__ float sigmoidf_(float x){ return 1.0f/(1.0f + expf(-x)); }
__device__ __forceinline__ float dot4_(float4 a, float4 b){
    return a.x*b.x + a.y*b.y + a.z*b.z + a.w*b.w;
}

/* ---------------------- 1. slots = mu + exp(ls)*noise ------------------- */
__global__ void k_init_slots(const float* __restrict__ noise,
                             const float* __restrict__ mu,
                             const float* __restrict__ lsig){
    int i = blockIdx.x*256 + threadIdx.x;             /* 131072 total */
    int s = i & (SDIM-1);
    g_slots[i] = mu[s] + expf(lsig[s]) * noise[i];
}

/* ---------------------- 2. LN row stats of inputs ----------------------- */
__global__ void k_rowstats(const float* __restrict__ inp){
    int row  = blockIdx.x*8 + (threadIdx.x >> 5);
    int lane = threadIdx.x & 31;
    const float4* p = (const float4*)(inp + (size_t)row*DIM);
    float s = 0.f, q = 0.f;
#pragma unroll
    for (int j=0;j<2;j++){
        float4 a = p[lane + 32*j];
        s += a.x+a.y+a.z+a.w;
        q += a.x*a.x + a.y*a.y + a.z*a.z + a.w*a.w;
    }
#pragma unroll
    for (int o=16;o;o>>=1){
        s += __shfl_xor_sync(0xffffffffu, s, o);
        q += __shfl_xor_sync(0xffffffffu, q, o);
    }
    if (lane==0){
        float m = s*(1.0f/DIM);
        float v = q*(1.0f/DIM) - m*m;
        g_mean[row] = m;
        g_rstd[row] = rsqrtf(v + LNEPS);
    }
}

/* ------ 3. fused LN + [k|v] projection: C[262144,512] = LN(A) @ Wcat^T -- */
/* BM=128 BN=128 BK=8, 256 threads, 8x8 per thread. blockIdx.x<2 -> k tile  */
__global__ __launch_bounds__(256) void k_kvgemm(const float* __restrict__ inp,
        const float* __restrict__ Wk, const float* __restrict__ Wv,
        const float* __restrict__ gin, const float* __restrict__ bin){
    __shared__ float As[8][128];
    __shared__ float Bs[8][128];
    int tid = threadIdx.x;
    int m0 = blockIdx.y * 128;
    int n0 = blockIdx.x * 128;
    int ar = tid >> 1;             /* 0..127 */
    int ac = (tid & 1) * 4;        /* 0 or 4 */
    int tx = tid & 15, ty = tid >> 4;

    int arow = m0 + ar;
    float mean = g_mean[arow], rstd = g_rstd[arow];
    const float4* Arow = (const float4*)(inp + (size_t)arow*DIM);
    int bj = n0 + ar;
    const float4* Brow = (bj < 256) ? (const float4*)(Wk + (size_t)bj*DIM)
                                    : (const float4*)(Wv + (size_t)(bj-256)*DIM);
    float acc[8][8];
#pragma unroll
    for (int i=0;i<8;i++)
#pragma unroll
        for (int j=0;j<8;j++) acc[i][j]=0.f;

    for (int k0=0; k0<DIM; k0+=8){
        float4 a4 = Arow[(k0+ac)>>2];
        float4 g4 = *(const float4*)(gin + k0 + ac);
        float4 o4 = *(const float4*)(bin + k0 + ac);
        As[ac+0][ar] = (a4.x-mean)*rstd*g4.x + o4.x;
        As[ac+1][ar] = (a4.y-mean)*rstd*g4.y + o4.y;
        As[ac+2][ar] = (a4.z-mean)*rstd*g4.z + o4.z;
        As[ac+3][ar] = (a4.w-mean)*rstd*g4.w + o4.w;
        float4 b4 = Brow[(k0+ac)>>2];
        Bs[ac+0][ar] = b4.x;
        Bs[ac+1][ar] = b4.y;
        Bs[ac+2][ar] = b4.z;
        Bs[ac+3][ar] = b4.w;
        __syncthreads();
#pragma unroll
        for (int kk=0; kk<8; kk++){
            float a[8], b[8];
            *(float4*)&a[0] = *(const float4*)&As[kk][ty*8];
            *(float4*)&a[4] = *(const float4*)&As[kk][ty*8+4];
            *(float4*)&b[0] = *(const float4*)&Bs[kk][tx*8];
            *(float4*)&b[4] = *(const float4*)&Bs[kk][tx*8+4];
#pragma unroll
            for (int i=0;i<8;i++)
#pragma unroll
                for (int j=0;j<8;j++) acc[i][j] += a[i]*b[j];
        }
        __syncthreads();
    }
    bool is_k = (blockIdx.x < 2);
    float scale = is_k ? 0.0625f : 1.0f;   /* S^-0.5 = 1/16 folded into k */
    int cbase = is_k ? (n0 + tx*8) : (n0 - 256 + tx*8);
#pragma unroll
    for (int i=0;i<8;i++){
        size_t r = (size_t)(m0 + ty*8 + i);
        float* dst = (is_k ? g_k : g_v) + (r<<8) + cbase;
        float4 v0 = make_float4(acc[i][0]*scale, acc[i][1]*scale,
                                acc[i][2]*scale, acc[i][3]*scale);
        float4 v1 = make_float4(acc[i][4]*scale, acc[i][5]*scale,
                                acc[i][6]*scale, acc[i][7]*scale);
        *(float4*)dst     = v0;
        *(float4*)(dst+4) = v1;
    }
}

/* ---------------------- 4. q = LN(slots) @ Wq^T ------------------------- */
__global__ __launch_bounds__(256) void k_q(const float* __restrict__ Wq,
        const float* __restrict__ gsl, const float* __restrict__ bsl){
    int r = blockIdx.x, t = threadIdx.x;
    int warp = t>>5, lane = t&31;
    __shared__ float xs[256];
    __shared__ float rs_[8], rq_[8];
    __shared__ float mv[2];
    float x = g_slots[r*256 + t];
    float s = x, q = x*x;
#pragma unroll
    for (int o=16;o;o>>=1){
        s += __shfl_xor_sync(0xffffffffu, s, o);
        q += __shfl_xor_sync(0xffffffffu, q, o);
    }
    if (lane==0){ rs_[warp]=s; rq_[warp]=q; }
    __syncthreads();
    if (t==0){
        float S=0.f,Q=0.f;
#pragma unroll
        for (int w=0;w<8;w++){ S+=rs_[w]; Q+=rq_[w]; }
        float m = S*(1.0f/256.f);
        mv[0]=m; mv[1]=rsqrtf(Q*(1.0f/256.f)-m*m+LNEPS);
    }
    __syncthreads();
    xs[t] = (x - mv[0])*mv[1]*gsl[t] + bsl[t];
    __syncthreads();
    float acc = 0.f;
    const float4* w = (const float4*)(Wq + (size_t)t*256);
#pragma unroll 8
    for (int d=0; d<64; d++)
        acc += dot4_(w[d], *(const float4*)&xs[d*4]);
    g_q[r*256 + t] = acc;
}

/* ------- 5. logits + softmax(over 8 slots) + EPS + partial colsum ------- */
__global__ __launch_bounds__(256) void k_attn(){
    int b = blockIdx.y, chunk = blockIdx.x;
    int warp = threadIdx.x>>5, lane = threadIdx.x&31;
    __shared__ float cs_s[8][8];
    float qreg[8][8];
#pragma unroll
    for (int kk=0;kk<8;kk++)
#pragma unroll
        for (int j=0;j<8;j++)
            qreg[kk][j] = g_q[((b<<3)+kk)*256 + lane + (j<<5)];
    float csum[8];
#pragma unroll
    for (int kk=0;kk<8;kk++) csum[kk]=0.f;
    int n0 = chunk*512 + warp*64;
    for (int i=0;i<64;i++){
        size_t row = (size_t)(b*NTOK + n0 + i);
        const float* kp = g_k + (row<<8);
        float lg[8];
#pragma unroll
        for (int kk=0;kk<8;kk++) lg[kk]=0.f;
#pragma unroll
        for (int j=0;j<8;j++){
            float kv = kp[lane + (j<<5)];
#pragma unroll
            for (int kk=0;kk<8;kk++) lg[kk] += kv * qreg[kk][j];
        }
#pragma unroll
        for (int kk=0;kk<8;kk++){
#pragma unroll
            for (int o=16;o;o>>=1)
                lg[kk] += __shfl_xor_sync(0xffffffffu, lg[kk], o);
        }
        if (lane==0){
            float m = lg[0];
#pragma unroll
            for (int kk=1;kk<8;kk++) m = fmaxf(m, lg[kk]);
            float e[8]; float ssum = 0.f;
#pragma unroll
            for (int kk=0;kk<8;kk++){ e[kk] = expf(lg[kk]-m); ssum += e[kk]; }
            float inv = 1.0f/ssum;
            float a[8];
#pragma unroll
            for (int kk=0;kk<8;kk++){ a[kk] = e[kk]*inv + EPSA; csum[kk] += a[kk]; }
            float4 o0 = make_float4(a[0],a[1],a[2],a[3]);
            float4 o1 = make_float4(a[4],a[5],a[6],a[7]);
            float* dst = g_attn + row*KSLOT;
            *(float4*)dst     = o0;
            *(float4*)(dst+4) = o1;
        }
    }
    if (lane==0){
#pragma unroll
        for (int kk=0;kk<8;kk++) cs_s[warp][kk] = csum[kk];
    }
    __syncthreads();
    if (threadIdx.x < 8){
        float s = 0.f;
#pragma unroll
        for (int w=0;w<8;w++) s += cs_s[w][threadIdx.x];
        g_cspart[(b*NCHUNK + chunk)*KSLOT + threadIdx.x] = s;
    }
}

/* ------------- 6. partial updates: per-chunk attn^T @ v ---------------- */
__global__ __launch_bounds__(256) void k_updpart(){
    int b = blockIdx.y, chunk = blockIdx.x, t = threadIdx.x;
    __shared__ float4 am[512][2];
    const float4* src = (const float4*)(g_attn + ((size_t)(b*NTOK + chunk*512))*KSLOT);
    for (int i=t; i<1024; i+=256) ((float4*)am)[i] = src[i];
    __syncthreads();
    float acc[8];
#pragma unroll
    for (int kk=0;kk<8;kk++) acc[kk]=0.f;
    size_t vbase = ((size_t)(b*NTOK + chunk*512))<<8;
    for (int n=0;n<512;n++){
        float vv = g_v[vbase + ((size_t)n<<8) + t];
        float4 a0 = am[n][0], a1 = am[n][1];
        acc[0] += a0.x*vv; acc[1] += a0.y*vv; acc[2] += a0.z*vv; acc[3] += a0.w*vv;
        acc[4] += a1.x*vv; acc[5] += a1.y*vv; acc[6] += a1.z*vv; acc[7] += a1.w*vv;
    }
#pragma unroll
    for (int kk=0;kk<8;kk++)
        g_updpart[(((size_t)chunk*BATCH + b)*KSLOT + kk)*256 + t] = acc[kk];
}

/* ------------- 7. reduce partials, divide by colsum -------------------- */
__global__ void k_updreduce(){
    int i = blockIdx.x*256 + threadIdx.x;   /* 131072 */
    int s  = i & 255;
    int bk = i >> 8;
    int b  = bk >> 3;
    int kk = bk & 7;
    float cs = 0.f;
#pragma unroll
    for (int c=0;c<NCHUNK;c++) cs += g_cspart[(b*NCHUNK + c)*KSLOT + kk];
    float sum = 0.f;
#pragma unroll
    for (int c=0;c<NCHUNK;c++)
        sum += g_updpart[(((size_t)c*BATCH + b)*KSLOT + kk)*256 + s];
    g_upd[i] = sum / cs;
}

/* ------------- 8. GRU cell + optional MLP residual --------------------- */
/* 4 rows per block, 128 blocks */
__global__ __launch_bounds__(256) void k_gru(
        const float* __restrict__ Wih, const float* __restrict__ Whh,
        const float* __restrict__ bih, const float* __restrict__ bhh,
        const float* __restrict__ W1,  const float* __restrict__ b1,
        const float* __restrict__ W2,  const float* __restrict__ b2,
        const float* __restrict__ gm,  const float* __restrict__ bm,
        int do_mlp, float* __restrict__ out){
    int t = threadIdx.x;
    int r0 = blockIdx.x * 4;
    __shared__ float Xs[4][256];   /* updates -> later new slots            */
    __shared__ float Hs[4][256];   /* prev slots -> later LN(new slots)     */
    __shared__ float Hm[4][512];   /* MLP hidden                            */
    __shared__ float mred[4][2];
    for (int i=t; i<1024; i+=256){
        ((float*)Xs)[i] = g_upd  [r0*256 + i];
        ((float*)Hs)[i] = g_slots[r0*256 + i];
    }
    __syncthreads();

    float gi_[3][4], gh_[3][4];
#pragma unroll
    for (int g=0; g<3; g++){
        float ai[4]={0,0,0,0}, ah[4]={0,0,0,0};
        const float4* wi = (const float4*)(Wih + ((size_t)((g<<8)+t))*256);
        const float4* wh = (const float4*)(Whh + ((size_t)((g<<8)+t))*256);
#pragma unroll 4
        for (int d=0; d<64; d++){
            float4 a = wi[d], c = wh[d];
#pragma unroll
            for (int r=0;r<4;r++){
                float4 xv = *(const float4*)&Xs[r][d<<2];
                float4 hv = *(const float4*)&Hs[r][d<<2];
                ai[r] += a.x*xv.x + a.y*xv.y + a.z*xv.z + a.w*xv.w;
                ah[r] += c.x*hv.x + c.y*hv.y + c.z*hv.z + c.w*hv.w;
            }
        }
        float bi = bih[(g<<8)+t], bh = bhh[(g<<8)+t];
#pragma unroll
        for (int r=0;r<4;r++){ gi_[g][r] = ai[r]+bi; gh_[g][r] = ah[r]+bh; }
    }
    __syncthreads();   /* all threads done reading Xs/Hs columns */

    float newv[4];
#pragma unroll
    for (int r=0;r<4;r++){
        float h  = Hs[r][t];
        float rr = sigmoidf_(gi_[0][r] + gh_[0][r]);
        float zz = sigmoidf_(gi_[1][r] + gh_[1][r]);
        float nn = tanhf(gi_[2][r] + rr*gh_[2][r]);
        newv[r] = (1.0f - zz)*nn + zz*h;
    }
#pragma unroll
    for (int r=0;r<4;r++) Xs[r][t] = newv[r];   /* Xs := new slots */

    if (!do_mlp){
#pragma unroll
        for (int r=0;r<4;r++){
            g_slots[(r0+r)*256 + t] = newv[r];
            if (out) out[(r0+r)*256 + t] = newv[r];
        }
        return;
    }
    __syncthreads();
    /* LN per row of new slots */
    int warp = t>>5, lane = t&31;
    if (warp < 4){
        float s=0.f, q=0.f;
#pragma unroll
        for (int j=0;j<8;j++){
            float xv = Xs[warp][lane + (j<<5)];
            s += xv; q += xv*xv;
        }
#pragma unroll
        for (int o=16;o;o>>=1){
            s += __shfl_xor_sync(0xffffffffu, s, o);
            q += __shfl_xor_sync(0xffffffffu, q, o);
        }
        if (lane==0){
            float m = s*(1.0f/256.f);
            mred[warp][0] = m;
            mred[warp][1] = rsqrtf(q*(1.0f/256.f) - m*m + LNEPS);
        }
    }
    __syncthreads();
    float gmt = gm[t], bmt = bm[t];
#pragma unroll
    for (int r=0;r<4;r++)
        Hs[r][t] = (Xs[r][t] - mred[r][0])*mred[r][1]*gmt + bmt;
    __syncthreads();
    /* hidden layer: each thread computes outputs t and t+256 */
#pragma unroll
    for (int hblk=0; hblk<2; hblk++){
        int ho = t + (hblk<<8);
        float acc[4]={0,0,0,0};
        const float4* w = (const float4*)(W1 + (size_t)ho*256);
#pragma unroll 4
        for (int d=0; d<64; d++){
            float4 a = w[d];
#pragma unroll
            for (int r=0;r<4;r++)
                acc[r] += dot4_(a, *(const float4*)&Hs[r][d<<2]);
        }
        float bb = b1[ho];
#pragma unroll
        for (int r=0;r<4;r++) Hm[r][ho] = fmaxf(acc[r]+bb, 0.f);
    }
    __syncthreads();
    /* output layer + residual */
    {
        float acc[4]={0,0,0,0};
        const float4* w = (const float4*)(W2 + (size_t)t*512);
#pragma unroll 4
        for (int j=0; j<128; j++){
            float4 a = w[j];
#pragma unroll
            for (int r=0;r<4;r++)
                acc[r] += dot4_(a, *(const float4*)&Hm[r][j<<2]);
        }
        float bb = b2[t];
#pragma unroll
        for (int r=0;r<4;r++)
            g_slots[(r0+r)*256 + t] = Xs[r][t] + acc[r] + bb;
    }
}

/* ----------------------------- launcher -------------------------------- */
extern "C" void kernel_launch(void* const* d_in, const int* in_sizes, int n_in,
                              void* d_out, int out_size){
    (void)in_sizes; (void)n_in; (void)out_size;
    const float* inputs = (const float*)d_in[0];
    const float* noise  = (const float*)d_in[1];
    const float* mu     = (const float*)d_in[2];
    const float* lsig   = (const float*)d_in[3];
    const float* gin    = (const float*)d_in[4];
    const float* bin    = (const float*)d_in[5];
    const float* gsl    = (const float*)d_in[6];
    const float* bsl    = (const float*)d_in[7];
    const float* gm     = (const float*)d_in[8];
    const float* bm     = (const float*)d_in[9];
    const float* Wq     = (const float*)d_in[10];
    const float* Wk     = (const float*)d_in[11];
    const float* Wv     = (const float*)d_in[12];
    const float* Wih    = (const float*)d_in[13];
    const float* Whh    = (const float*)d_in[14];
    const float* bih    = (const float*)d_in[15];
    const float* bhh    = (const float*)d_in[16];
    const float* W1     = (const float*)d_in[17];
    const float* b1     = (const float*)d_in[18];
    const float* W2     = (const float*)d_in[19];
    const float* b2     = (const float*)d_in[20];
    float* out = (float*)d_out;

    k_init_slots<<<512, 256>>>(noise, mu, lsig);
    k_rowstats<<<NROWS/8, 256>>>(inputs);
    k_kvgemm<<<dim3(4, NROWS/128), 256>>>(inputs, Wk, Wv, gin, bin);
    for (int it=0; it<3; it++){
        k_q<<<BATCH*KSLOT, 256>>>(Wq, gsl, bsl);
        k_attn<<<dim3(NCHUNK, BATCH), 256>>>();
        k_updpart<<<dim3(NCHUNK, BATCH), 256>>>();
        k_updreduce<<<512, 256>>>();
        k_gru<<<128, 256>>>(Wih, Whh, bih, bhh, W1, b1, W2, b2, gm, bm,
                            (it < 2) ? 1 : 0, (it == 2) ? out : nullptr);
    }
}

// round 4
// speedup vs baseline: 1.4426x; 1.4426x over previous
#include <cuda_runtime.h>
#include <cuda_bf16.h>
#include <math.h>
#include <stddef.h>

#define BATCH  64
#define NTOK   4096
#define DIM    256
#define SDIM   256
#define KSLOT  8
#define HID    512
#define EPSA   1e-8f
#define LNEPS  1e-5f
#define NROWS  (BATCH*NTOK)       /* 262144 */
#define NCHUNK 8

/* ------------- scratch (device globals; no allocation allowed) ---------- */
__device__ __align__(16) float g_k[NROWS*SDIM];                 /* 256 MB */
__device__ __align__(16) float g_v[NROWS*SDIM];                 /* 256 MB */
__device__ __align__(16) float g_attn[NROWS*KSLOT];             /* 8 MB   */
__device__ __align__(16) float g_slots[BATCH*KSLOT*SDIM];
__device__ __align__(16) float g_q[BATCH*KSLOT*SDIM];
__device__ __align__(16) float g_upd[BATCH*KSLOT*SDIM];
__device__ __align__(16) float g_updpart[NCHUNK*BATCH*KSLOT*SDIM];
__device__ __align__(16) float g_cspart[BATCH*NCHUNK*KSLOT];
/* bf16 split operands for the KV GEMM */
__device__ __align__(16) __nv_bfloat16 g_Ah[(size_t)NROWS*DIM]; /* 128 MB */
__device__ __align__(16) __nv_bfloat16 g_Al[(size_t)NROWS*DIM]; /* 128 MB */
__device__ __align__(16) __nv_bfloat16 g_Wh[512*256];
__device__ __align__(16) __nv_bfloat16 g_Wl[512*256];
__device__ __align__(16) float g_cb[512];

__device__ __forceinline__ float sigmoidf_(float x){ return 1.0f/(1.0f + expf(-x)); }
__device__ __forceinline__ float dot4_(float4 a, float4 b){
    return a.x*b.x + a.y*b.y + a.z*b.z + a.w*b.w;
}

/* ----------------------- PTX helpers ----------------------------------- */
__device__ __forceinline__ unsigned smem_u32(const void* p){
    return (unsigned)__cvta_generic_to_shared(p);
}
__device__ __forceinline__ void cp16(unsigned dst, const void* src){
    asm volatile("cp.async.cg.shared.global [%0],[%1],16;\n"::"r"(dst),"l"(src));
}
__device__ __forceinline__ void cp_commit(){ asm volatile("cp.async.commit_group;\n"::); }
__device__ __forceinline__ void cp_wait1(){ asm volatile("cp.async.wait_group 1;\n"::); }
__device__ __forceinline__ void cp_wait0(){ asm volatile("cp.async.wait_group 0;\n"::); }
__device__ __forceinline__ void ldm4(unsigned&r0,unsigned&r1,unsigned&r2,unsigned&r3,unsigned a){
    asm volatile("ldmatrix.sync.aligned.m8n8.x4.shared.b16 {%0,%1,%2,%3},[%4];\n"
        :"=r"(r0),"=r"(r1),"=r"(r2),"=r"(r3):"r"(a));
}
__device__ __forceinline__ void mma16816(float* c, const unsigned* a, unsigned b0, unsigned b1){
    asm volatile("mma.sync.aligned.m16n8k16.row.col.f32.bf16.bf16.f32 "
        "{%0,%1,%2,%3},{%4,%5,%6,%7},{%8,%9},{%0,%1,%2,%3};\n"
        :"+f"(c[0]),"+f"(c[1]),"+f"(c[2]),"+f"(c[3])
        :"r"(a[0]),"r"(a[1]),"r"(a[2]),"r"(a[3]),"r"(b0),"r"(b1));
}

/* ---------------------- 1. slots = mu + exp(ls)*noise ------------------- */
__global__ void k_init_slots(const float* __restrict__ noise,
                             const float* __restrict__ mu,
                             const float* __restrict__ lsig){
    int i = blockIdx.x*256 + threadIdx.x;
    int s = i & (SDIM-1);
    g_slots[i] = mu[s] + expf(lsig[s]) * noise[i];
}

/* ------------- 2. LN(inputs) -> bf16 hi/lo split ----------------------- */
__global__ __launch_bounds__(256) void k_prep_a(const float* __restrict__ inp){
    int row  = blockIdx.x*8 + (threadIdx.x >> 5);
    int lane = threadIdx.x & 31;
    const float4* p = (const float4*)(inp + (size_t)row*DIM);
    float4 a = p[lane*2], b = p[lane*2+1];
    float x[8] = {a.x,a.y,a.z,a.w,b.x,b.y,b.z,b.w};
    float s = 0.f, q = 0.f;
#pragma unroll
    for (int i=0;i<8;i++){ s += x[i]; q += x[i]*x[i]; }
#pragma unroll
    for (int o=16;o;o>>=1){
        s += __shfl_xor_sync(0xffffffffu, s, o);
        q += __shfl_xor_sync(0xffffffffu, q, o);
    }
    float m = s*(1.0f/DIM);
    float rstd = rsqrtf(q*(1.0f/DIM) - m*m + LNEPS);
    __nv_bfloat162 h2[4], l2[4];
#pragma unroll
    for (int i=0;i<4;i++){
        float xn0 = (x[2*i]   - m)*rstd;
        float xn1 = (x[2*i+1] - m)*rstd;
        __nv_bfloat16 h0 = __float2bfloat16(xn0);
        __nv_bfloat16 h1 = __float2bfloat16(xn1);
        __nv_bfloat16 l0 = __float2bfloat16(xn0 - __bfloat162float(h0));
        __nv_bfloat16 l1 = __float2bfloat16(xn1 - __bfloat162float(h1));
        h2[i] = __halves2bfloat162(h0, h1);
        l2[i] = __halves2bfloat162(l0, l1);
    }
    size_t off = (size_t)row*DIM + lane*8;
    *(uint4*)(g_Ah + off) = *(uint4*)h2;
    *(uint4*)(g_Al + off) = *(uint4*)l2;
}

/* ------------- 3. fold gamma/scale into W, split to bf16 --------------- */
__global__ __launch_bounds__(256) void k_prep_w(const float* __restrict__ Wk,
        const float* __restrict__ Wv, const float* __restrict__ gin,
        const float* __restrict__ bin){
    int n    = blockIdx.x*8 + (threadIdx.x >> 5);   /* 0..511 */
    int lane = threadIdx.x & 31;
    const float* W = (n < 256) ? (Wk + (size_t)n*DIM) : (Wv + (size_t)(n-256)*DIM);
    float scale = (n < 256) ? 0.0625f : 1.0f;       /* S^-0.5 folded into k */
    const float4* wp = (const float4*)W;
    const float4* gp = (const float4*)gin;
    const float4* bp = (const float4*)bin;
    float4 w0 = wp[lane*2], w1 = wp[lane*2+1];
    float4 gg0 = gp[lane*2], gg1 = gp[lane*2+1];
    float4 bb0 = bp[lane*2], bb1 = bp[lane*2+1];
    float w[8]  = {w0.x,w0.y,w0.z,w0.w,w1.x,w1.y,w1.z,w1.w};
    float gv[8] = {gg0.x,gg0.y,gg0.z,gg0.w,gg1.x,gg1.y,gg1.z,gg1.w};
    float bv[8] = {bb0.x,bb0.y,bb0.z,bb0.w,bb1.x,bb1.y,bb1.z,bb1.w};
    float bsum = 0.f;
    __nv_bfloat162 h2[4], l2[4];
#pragma unroll
    for (int i=0;i<4;i++){
        float v0 = w[2*i]*gv[2*i]*scale;
        float v1 = w[2*i+1]*gv[2*i+1]*scale;
        bsum += w[2*i]*bv[2*i] + w[2*i+1]*bv[2*i+1];
        __nv_bfloat16 h0 = __float2bfloat16(v0);
        __nv_bfloat16 h1 = __float2bfloat16(v1);
        __nv_bfloat16 l0 = __float2bfloat16(v0 - __bfloat162float(h0));
        __nv_bfloat16 l1 = __float2bfloat16(v1 - __bfloat162float(h1));
        h2[i] = __halves2bfloat162(h0, h1);
        l2[i] = __halves2bfloat162(l0, l1);
    }
#pragma unroll
    for (int o=16;o;o>>=1) bsum += __shfl_xor_sync(0xffffffffu, bsum, o);
    if (lane==0) g_cb[n] = bsum*scale;
    size_t off = (size_t)n*DIM + lane*8;
    *(uint4*)(g_Wh + off) = *(uint4*)h2;
    *(uint4*)(g_Wl + off) = *(uint4*)l2;
}

/* ------------- 4. tensor-core KV GEMM (bf16x3 split) -------------------- */
/* C[262144,512] = A @ Wc^T ; BM=128 BN=128 BK=32, 8 warps (4m x 2n),       */
/* warp tile 32x64, smem stride 40 bf16 (conflict-free ldmatrix)            */
#define LDSB 40
#define STAGE_BYTES 40960   /* 4 arrays * 128*40*2 */
__global__ __launch_bounds__(256,1) void k_kvgemm_mma(){
    extern __shared__ __align__(16) char smem_raw[];
    const unsigned sbase = smem_u32(smem_raw);
    const int tid  = threadIdx.x;
    const int warp = tid>>5, lane = tid&31;
    const int m0 = blockIdx.y*128;
    const int n0 = blockIdx.x*128;
    const int wm = (warp&3)*32;
    const int wn = (warp>>2)*64;

    float acc[2][8][4];
#pragma unroll
    for (int i=0;i<2;i++)
#pragma unroll
        for (int j=0;j<8;j++)
#pragma unroll
            for (int c=0;c<4;c++) acc[i][j][c]=0.f;

    auto load_stage = [&](int st, int k0){
        unsigned base = sbase + st*STAGE_BYTES;
        int row = tid>>2, seg = tid&3;
#pragma unroll
        for (int p=0;p<2;p++){
            int r = row + p*64;
            size_t ga = ((size_t)(m0+r))*DIM + k0 + seg*8;
            size_t gw = ((size_t)(n0+r))*DIM + k0 + seg*8;
            unsigned dst = base + (unsigned)(r*80 + seg*16);
            cp16(dst,          g_Ah + ga);
            cp16(dst + 10240,  g_Al + ga);
            cp16(dst + 20480,  g_Wh + gw);
            cp16(dst + 30720,  g_Wl + gw);
        }
    };

    load_stage(0, 0);
    cp_commit();

#pragma unroll 1
    for (int kt=0; kt<8; kt++){
        if (kt < 7){ load_stage((kt+1)&1, (kt+1)*32); cp_commit(); cp_wait1(); }
        else cp_wait0();
        __syncthreads();
        unsigned base = sbase + (kt&1)*STAGE_BYTES;
#pragma unroll
        for (int ks=0; ks<32; ks+=16){
            unsigned ah[2][4], al[2][4];
#pragma unroll
            for (int mt=0;mt<2;mt++){
                unsigned addr = base + (unsigned)(((wm + mt*16 + (lane&15))*LDSB
                                         + ks + ((lane>>4)<<3))*2);
                ldm4(ah[mt][0],ah[mt][1],ah[mt][2],ah[mt][3], addr);
                ldm4(al[mt][0],al[mt][1],al[mt][2],al[mt][3], addr + 10240);
            }
            unsigned bh[4][4], bl[4][4];
#pragma unroll
            for (int nt2=0;nt2<4;nt2++){
                unsigned addr = base + 20480u + (unsigned)(((wn + nt2*16 + (lane&15))*LDSB
                                         + ks + ((lane>>4)<<3))*2);
                ldm4(bh[nt2][0],bh[nt2][1],bh[nt2][2],bh[nt2][3], addr);
                ldm4(bl[nt2][0],bl[nt2][1],bl[nt2][2],bl[nt2][3], addr + 10240);
            }
#pragma unroll
            for (int mt=0;mt<2;mt++)
#pragma unroll
                for (int nt=0;nt<8;nt++){
                    int nt2 = nt>>1, pr = nt&1;
                    mma16816(acc[mt][nt], ah[mt], bh[nt2][pr], bh[nt2][pr+2]);
                    mma16816(acc[mt][nt], ah[mt], bl[nt2][pr], bl[nt2][pr+2]);
                    mma16816(acc[mt][nt], al[mt], bh[nt2][pr], bh[nt2][pr+2]);
                }
        }
        __syncthreads();
    }

    /* epilogue: add folded bias, write fp32 to g_k / g_v */
    bool isk = (n0 < 256);
    float* Cb = isk ? g_k : g_v;
    int ncol0 = isk ? n0 : (n0 - 256);
#pragma unroll
    for (int mt=0;mt<2;mt++){
        int r = m0 + wm + mt*16 + (lane>>2);
#pragma unroll
        for (int nt=0;nt<8;nt++){
            int nl = wn + nt*8 + (lane&3)*2;
            int gn = n0 + nl;
            float bx = g_cb[gn], by = g_cb[gn+1];
            float* d0 = Cb + (((size_t)r)<<8) + ncol0 + nl;
            float* d1 = Cb + (((size_t)(r+8))<<8) + ncol0 + nl;
            *(float2*)d0 = make_float2(acc[mt][nt][0]+bx, acc[mt][nt][1]+by);
            *(float2*)d1 = make_float2(acc[mt][nt][2]+bx, acc[mt][nt][3]+by);
        }
    }
}

/* ---------------------- 5. q = LN(slots) @ Wq^T ------------------------- */
__global__ __launch_bounds__(256) void k_q(const float* __restrict__ Wq,
        const float* __restrict__ gsl, const float* __restrict__ bsl){
    int r = blockIdx.x, t = threadIdx.x;
    int warp = t>>5, lane = t&31;
    __shared__ float xs[256];
    __shared__ float rs_[8], rq_[8];
    __shared__ float mv[2];
    float x = g_slots[r*256 + t];
    float s = x, q = x*x;
#pragma unroll
    for (int o=16;o;o>>=1){
        s += __shfl_xor_sync(0xffffffffu, s, o);
        q += __shfl_xor_sync(0xffffffffu, q, o);
    }
    if (lane==0){ rs_[warp]=s; rq_[warp]=q; }
    __syncthreads();
    if (t==0){
        float S=0.f,Q=0.f;
#pragma unroll
        for (int w=0;w<8;w++){ S+=rs_[w]; Q+=rq_[w]; }
        float m = S*(1.0f/256.f);
        mv[0]=m; mv[1]=rsqrtf(Q*(1.0f/256.f)-m*m+LNEPS);
    }
    __syncthreads();
    xs[t] = (x - mv[0])*mv[1]*gsl[t] + bsl[t];
    __syncthreads();
    float acc = 0.f;
    const float4* w = (const float4*)(Wq + (size_t)t*256);
#pragma unroll 8
    for (int d=0; d<64; d++)
        acc += dot4_(w[d], *(const float4*)&xs[d*4]);
    g_q[r*256 + t] = acc;
}

/* ------- 6. logits + softmax(over 8 slots) + EPS + partial colsum ------- */
__global__ __launch_bounds__(256) void k_attn(){
    int b = blockIdx.y, chunk = blockIdx.x;
    int warp = threadIdx.x>>5, lane = threadIdx.x&31;
    __shared__ float cs_s[8][8];
    float qreg[8][8];
#pragma unroll
    for (int kk=0;kk<8;kk++)
#pragma unroll
        for (int j=0;j<8;j++)
            qreg[kk][j] = g_q[((b<<3)+kk)*256 + lane + (j<<5)];
    float csum[8];
#pragma unroll
    for (int kk=0;kk<8;kk++) csum[kk]=0.f;
    int n0 = chunk*512 + warp*64;
    for (int i=0;i<64;i++){
        size_t row = (size_t)(b*NTOK + n0 + i);
        const float* kp = g_k + (row<<8);
        float lg[8];
#pragma unroll
        for (int kk=0;kk<8;kk++) lg[kk]=0.f;
#pragma unroll
        for (int j=0;j<8;j++){
            float kv = kp[lane + (j<<5)];
#pragma unroll
            for (int kk=0;kk<8;kk++) lg[kk] += kv * qreg[kk][j];
        }
#pragma unroll
        for (int kk=0;kk<8;kk++){
#pragma unroll
            for (int o=16;o;o>>=1)
                lg[kk] += __shfl_xor_sync(0xffffffffu, lg[kk], o);
        }
        if (lane==0){
            float m = lg[0];
#pragma unroll
            for (int kk=1;kk<8;kk++) m = fmaxf(m, lg[kk]);
            float e[8]; float ssum = 0.f;
#pragma unroll
            for (int kk=0;kk<8;kk++){ e[kk] = expf(lg[kk]-m); ssum += e[kk]; }
            float inv = 1.0f/ssum;
            float a[8];
#pragma unroll
            for (int kk=0;kk<8;kk++){ a[kk] = e[kk]*inv + EPSA; csum[kk] += a[kk]; }
            float4 o0 = make_float4(a[0],a[1],a[2],a[3]);
            float4 o1 = make_float4(a[4],a[5],a[6],a[7]);
            float* dst = g_attn + row*KSLOT;
            *(float4*)dst     = o0;
            *(float4*)(dst+4) = o1;
        }
    }
    if (lane==0){
#pragma unroll
        for (int kk=0;kk<8;kk++) cs_s[warp][kk] = csum[kk];
    }
    __syncthreads();
    if (threadIdx.x < 8){
        float s = 0.f;
#pragma unroll
        for (int w=0;w<8;w++) s += cs_s[w][threadIdx.x];
        g_cspart[(b*NCHUNK + chunk)*KSLOT + threadIdx.x] = s;
    }
}

/* ------------- 7. partial updates: per-chunk attn^T @ v ---------------- */
__global__ __launch_bounds__(256) void k_updpart(){
    int b = blockIdx.y, chunk = blockIdx.x, t = threadIdx.x;
    __shared__ float4 am[512][2];
    const float4* src = (const float4*)(g_attn + ((size_t)(b*NTOK + chunk*512))*KSLOT);
    for (int i=t; i<1024; i+=256) ((float4*)am)[i] = src[i];
    __syncthreads();
    float acc[8];
#pragma unroll
    for (int kk=0;kk<8;kk++) acc[kk]=0.f;
    size_t vbase = ((size_t)(b*NTOK + chunk*512))<<8;
    for (int n=0;n<512;n++){
        float vv = g_v[vbase + ((size_t)n<<8) + t];
        float4 a0 = am[n][0], a1 = am[n][1];
        acc[0] += a0.x*vv; acc[1] += a0.y*vv; acc[2] += a0.z*vv; acc[3] += a0.w*vv;
        acc[4] += a1.x*vv; acc[5] += a1.y*vv; acc[6] += a1.z*vv; acc[7] += a1.w*vv;
    }
#pragma unroll
    for (int kk=0;kk<8;kk++)
        g_updpart[(((size_t)chunk*BATCH + b)*KSLOT + kk)*256 + t] = acc[kk];
}

/* ------------- 8. reduce partials, divide by colsum -------------------- */
__global__ void k_updreduce(){
    int i = blockIdx.x*256 + threadIdx.x;   /* 131072 */
    int s  = i & 255;
    int bk = i >> 8;
    int b  = bk >> 3;
    int kk = bk & 7;
    float cs = 0.f;
#pragma unroll
    for (int c=0;c<NCHUNK;c++) cs += g_cspart[(b*NCHUNK + c)*KSLOT + kk];
    float sum = 0.f;
#pragma unroll
    for (int c=0;c<NCHUNK;c++)
        sum += g_updpart[(((size_t)c*BATCH + b)*KSLOT + kk)*256 + s];
    g_upd[i] = sum / cs;
}

/* ------------- 9. GRU cell + optional MLP residual --------------------- */
__global__ __launch_bounds__(256) void k_gru(
        const float* __restrict__ Wih, const float* __restrict__ Whh,
        const float* __restrict__ bih, const float* __restrict__ bhh,
        const float* __restrict__ W1,  const float* __restrict__ b1,
        const float* __restrict__ W2,  const float* __restrict__ b2,
        const float* __restrict__ gm,  const float* __restrict__ bm,
        int do_mlp, float* __restrict__ out){
    int t = threadIdx.x;
    int r0 = blockIdx.x * 4;
    __shared__ float Xs[4][256];
    __shared__ float Hs[4][256];
    __shared__ float Hm[4][512];
    __shared__ float mred[4][2];
    for (int i=t; i<1024; i+=256){
        ((float*)Xs)[i] = g_upd  [r0*256 + i];
        ((float*)Hs)[i] = g_slots[r0*256 + i];
    }
    __syncthreads();

    float gi_[3][4], gh_[3][4];
#pragma unroll
    for (int g=0; g<3; g++){
        float ai[4]={0,0,0,0}, ah[4]={0,0,0,0};
        const float4* wi = (const float4*)(Wih + ((size_t)((g<<8)+t))*256);
        const float4* wh = (const float4*)(Whh + ((size_t)((g<<8)+t))*256);
#pragma unroll 4
        for (int d=0; d<64; d++){
            float4 a = wi[d], c = wh[d];
#pragma unroll
            for (int r=0;r<4;r++){
                float4 xv = *(const float4*)&Xs[r][d<<2];
                float4 hv = *(const float4*)&Hs[r][d<<2];
                ai[r] += a.x*xv.x + a.y*xv.y + a.z*xv.z + a.w*xv.w;
                ah[r] += c.x*hv.x + c.y*hv.y + c.z*hv.z + c.w*hv.w;
            }
        }
        float bi = bih[(g<<8)+t], bh = bhh[(g<<8)+t];
#pragma unroll
        for (int r=0;r<4;r++){ gi_[g][r] = ai[r]+bi; gh_[g][r] = ah[r]+bh; }
    }
    __syncthreads();

    float newv[4];
#pragma unroll
    for (int r=0;r<4;r++){
        float h  = Hs[r][t];
        float rr = sigmoidf_(gi_[0][r] + gh_[0][r]);
        float zz = sigmoidf_(gi_[1][r] + gh_[1][r]);
        float nn = tanhf(gi_[2][r] + rr*gh_[2][r]);
        newv[r] = (1.0f - zz)*nn + zz*h;
    }
#pragma unroll
    for (int r=0;r<4;r++) Xs[r][t] = newv[r];

    if (!do_mlp){
#pragma unroll
        for (int r=0;r<4;r++){
            g_slots[(r0+r)*256 + t] = newv[r];
            if (out) out[(r0+r)*256 + t] = newv[r];
        }
        return;
    }
    __syncthreads();
    int warp = t>>5, lane = t&31;
    if (warp < 4){
        float s=0.f, q=0.f;
#pragma unroll
        for (int j=0;j<8;j++){
            float xv = Xs[warp][lane + (j<<5)];
            s += xv; q += xv*xv;
        }
#pragma unroll
        for (int o=16;o;o>>=1){
            s += __shfl_xor_sync(0xffffffffu, s, o);
            q += __shfl_xor_sync(0xffffffffu, q, o);
        }
        if (lane==0){
            float m = s*(1.0f/256.f);
            mred[warp][0] = m;
            mred[warp][1] = rsqrtf(q*(1.0f/256.f) - m*m + LNEPS);
        }
    }
    __syncthreads();
    float gmt = gm[t], bmt = bm[t];
#pragma unroll
    for (int r=0;r<4;r++)
        Hs[r][t] = (Xs[r][t] - mred[r][0])*mred[r][1]*gmt + bmt;
    __syncthreads();
#pragma unroll
    for (int hblk=0; hblk<2; hblk++){
        int ho = t + (hblk<<8);
        float acc[4]={0,0,0,0};
        const float4* w = (const float4*)(W1 + (size_t)ho*256);
#pragma unroll 4
        for (int d=0; d<64; d++){
            float4 a = w[d];
#pragma unroll
            for (int r=0;r<4;r++)
                acc[r] += dot4_(a, *(const float4*)&Hs[r][d<<2]);
        }
        float bb = b1[ho];
#pragma unroll
        for (int r=0;r<4;r++) Hm[r][ho] = fmaxf(acc[r]+bb, 0.f);
    }
    __syncthreads();
    {
        float acc[4]={0,0,0,0};
        const float4* w = (const float4*)(W2 + (size_t)t*512);
#pragma unroll 4
        for (int j=0; j<128; j++){
            float4 a = w[j];
#pragma unroll
            for (int r=0;r<4;r++)
                acc[r] += dot4_(a, *(const float4*)&Hm[r][j<<2]);
        }
        float bb = b2[t];
#pragma unroll
        for (int r=0;r<4;r++)
            g_slots[(r0+r)*256 + t] = Xs[r][t] + acc[r] + bb;
    }
}

/* ----------------------------- launcher -------------------------------- */
extern "C" void kernel_launch(void* const* d_in, const int* in_sizes, int n_in,
                              void* d_out, int out_size){
    (void)in_sizes; (void)n_in; (void)out_size;
    const float* inputs = (const float*)d_in[0];
    const float* noise  = (const float*)d_in[1];
    const float* mu     = (const float*)d_in[2];
    const float* lsig   = (const float*)d_in[3];
    const float* gin    = (const float*)d_in[4];
    const float* bin    = (const float*)d_in[5];
    const float* gsl    = (const float*)d_in[6];
    const float* bsl    = (const float*)d_in[7];
    const float* gm     = (const float*)d_in[8];
    const float* bm     = (const float*)d_in[9];
    const float* Wq     = (const float*)d_in[10];
    const float* Wk     = (const float*)d_in[11];
    const float* Wv     = (const float*)d_in[12];
    const float* Wih    = (const float*)d_in[13];
    const float* Whh    = (const float*)d_in[14];
    const float* bih    = (const float*)d_in[15];
    const float* bhh    = (const float*)d_in[16];
    const float* W1     = (const float*)d_in[17];
    const float* b1     = (const float*)d_in[18];
    const float* W2     = (const float*)d_in[19];
    const float* b2     = (const float*)d_in[20];
    float* out = (float*)d_out;

    cudaFuncSetAttribute(k_kvgemm_mma,
                         cudaFuncAttributeMaxDynamicSharedMemorySize, 2*STAGE_BYTES);

    k_init_slots<<<512, 256>>>(noise, mu, lsig);
    k_prep_a<<<NROWS/8, 256>>>(inputs);
    k_prep_w<<<64, 256>>>(Wk, Wv, gin, bin);
    k_kvgemm_mma<<<dim3(4, NROWS/128), 256, 2*STAGE_BYTES>>>();
    for (int it=0; it<3; it++){
        k_q<<<BATCH*KSLOT, 256>>>(Wq, gsl, bsl);
        k_attn<<<dim3(NCHUNK, BATCH), 256>>>();
        k_updpart<<<dim3(NCHUNK, BATCH), 256>>>();
        k_updreduce<<<512, 256>>>();
        k_gru<<<128, 256>>>(Wih, Whh, bih, bhh, W1, b1, W2, b2, gm, bm,
                            (it < 2) ? 1 : 0, (it == 2) ? out : nullptr);
    }
}

// round 5
// speedup vs baseline: 2.2269x; 1.5437x over previous
#include <cuda_runtime.h>
#include <cuda_bf16.h>
#include <math.h>
#include <stddef.h>

#define BATCH  64
#define NTOK   4096
#define DIM    256
#define SDIM   256
#define KSLOT  8
#define HID    512
#define EPSA   1e-8f
#define LNEPS  1e-5f
#define NROWS  (BATCH*NTOK)       /* 262144 */
#define NCHUNK 8

/* ------------- scratch (device globals; no allocation allowed) ---------- */
__device__ __align__(16) __nv_bfloat16 g_kb[(size_t)NROWS*SDIM];   /* 128 MB */
__device__ __align__(16) __nv_bfloat16 g_vb[(size_t)NROWS*SDIM];   /* 128 MB */
__device__ __align__(16) float g_attn[NROWS*KSLOT];                /* 8 MB   */
__device__ __align__(16) float g_slots[BATCH*KSLOT*SDIM];
__device__ __align__(16) float g_q[BATCH*KSLOT*SDIM];
__device__ __align__(16) float g_upd[BATCH*KSLOT*SDIM];
__device__ __align__(16) float g_updpart[NCHUNK*BATCH*KSLOT*SDIM];
__device__ __align__(16) float g_cspart[BATCH*NCHUNK*KSLOT];
/* bf16 operands for the KV GEMM */
__device__ __align__(16) __nv_bfloat16 g_Ah[(size_t)NROWS*DIM];    /* 128 MB */
__device__ __align__(16) __nv_bfloat16 g_Wh[512*256];
__device__ __align__(16) float g_cb[512];

__device__ __forceinline__ float sigmoidf_(float x){ return 1.0f/(1.0f + expf(-x)); }
__device__ __forceinline__ float dot4_(float4 a, float4 b){
    return a.x*b.x + a.y*b.y + a.z*b.z + a.w*b.w;
}

/* ----------------------- PTX helpers ----------------------------------- */
__device__ __forceinline__ unsigned smem_u32(const void* p){
    return (unsigned)__cvta_generic_to_shared(p);
}
__device__ __forceinline__ void cp16(unsigned dst, const void* src){
    asm volatile("cp.async.cg.shared.global [%0],[%1],16;\n"::"r"(dst),"l"(src));
}
__device__ __forceinline__ void cp_commit(){ asm volatile("cp.async.commit_group;\n"::); }
__device__ __forceinline__ void cp_wait2(){ asm volatile("cp.async.wait_group 2;\n"::); }
__device__ __forceinline__ void cp_wait1(){ asm volatile("cp.async.wait_group 1;\n"::); }
__device__ __forceinline__ void cp_wait0(){ asm volatile("cp.async.wait_group 0;\n"::); }
__device__ __forceinline__ void ldm4(unsigned&r0,unsigned&r1,unsigned&r2,unsigned&r3,unsigned a){
    asm volatile("ldmatrix.sync.aligned.m8n8.x4.shared.b16 {%0,%1,%2,%3},[%4];\n"
        :"=r"(r0),"=r"(r1),"=r"(r2),"=r"(r3):"r"(a));
}
__device__ __forceinline__ void mma16816(float* c, const unsigned* a, unsigned b0, unsigned b1){
    asm volatile("mma.sync.aligned.m16n8k16.row.col.f32.bf16.bf16.f32 "
        "{%0,%1,%2,%3},{%4,%5,%6,%7},{%8,%9},{%0,%1,%2,%3};\n"
        :"+f"(c[0]),"+f"(c[1]),"+f"(c[2]),"+f"(c[3])
        :"r"(a[0]),"r"(a[1]),"r"(a[2]),"r"(a[3]),"r"(b0),"r"(b1));
}

/* ---------------------- 1. slots = mu + exp(ls)*noise ------------------- */
__global__ void k_init_slots(const float* __restrict__ noise,
                             const float* __restrict__ mu,
                             const float* __restrict__ lsig){
    int i = blockIdx.x*256 + threadIdx.x;
    int s = i & (SDIM-1);
    g_slots[i] = mu[s] + expf(lsig[s]) * noise[i];
}

/* ------------- 2. LN(inputs) -> bf16 --------------------------------- */
__global__ __launch_bounds__(256) void k_prep_a(const float* __restrict__ inp){
    int row  = blockIdx.x*8 + (threadIdx.x >> 5);
    int lane = threadIdx.x & 31;
    const float4* p = (const float4*)(inp + (size_t)row*DIM);
    float4 a = p[lane*2], b = p[lane*2+1];
    float x[8] = {a.x,a.y,a.z,a.w,b.x,b.y,b.z,b.w};
    float s = 0.f, q = 0.f;
#pragma unroll
    for (int i=0;i<8;i++){ s += x[i]; q += x[i]*x[i]; }
#pragma unroll
    for (int o=16;o;o>>=1){
        s += __shfl_xor_sync(0xffffffffu, s, o);
        q += __shfl_xor_sync(0xffffffffu, q, o);
    }
    float m = s*(1.0f/DIM);
    float rstd = rsqrtf(q*(1.0f/DIM) - m*m + LNEPS);
    __nv_bfloat162 h2[4];
#pragma unroll
    for (int i=0;i<4;i++){
        float xn0 = (x[2*i]   - m)*rstd;
        float xn1 = (x[2*i+1] - m)*rstd;
        h2[i] = __halves2bfloat162(__float2bfloat16(xn0), __float2bfloat16(xn1));
    }
    size_t off = (size_t)row*DIM + lane*8;
    *(uint4*)(g_Ah + off) = *(uint4*)h2;
}

/* ------------- 3. fold gamma/scale into W, bf16 ------------------------ */
__global__ __launch_bounds__(256) void k_prep_w(const float* __restrict__ Wk,
        const float* __restrict__ Wv, const float* __restrict__ gin,
        const float* __restrict__ bin){
    int n    = blockIdx.x*8 + (threadIdx.x >> 5);   /* 0..511 */
    int lane = threadIdx.x & 31;
    const float* W = (n < 256) ? (Wk + (size_t)n*DIM) : (Wv + (size_t)(n-256)*DIM);
    float scale = (n < 256) ? 0.0625f : 1.0f;       /* S^-0.5 folded into k */
    const float4* wp = (const float4*)W;
    const float4* gp = (const float4*)gin;
    const float4* bp = (const float4*)bin;
    float4 w0 = wp[lane*2], w1 = wp[lane*2+1];
    float4 gg0 = gp[lane*2], gg1 = gp[lane*2+1];
    float4 bb0 = bp[lane*2], bb1 = bp[lane*2+1];
    float w[8]  = {w0.x,w0.y,w0.z,w0.w,w1.x,w1.y,w1.z,w1.w};
    float gv[8] = {gg0.x,gg0.y,gg0.z,gg0.w,gg1.x,gg1.y,gg1.z,gg1.w};
    float bv[8] = {bb0.x,bb0.y,bb0.z,bb0.w,bb1.x,bb1.y,bb1.z,bb1.w};
    float bsum = 0.f;
    __nv_bfloat162 h2[4];
#pragma unroll
    for (int i=0;i<4;i++){
        float v0 = w[2*i]*gv[2*i]*scale;
        float v1 = w[2*i+1]*gv[2*i+1]*scale;
        bsum += w[2*i]*bv[2*i] + w[2*i+1]*bv[2*i+1];
        h2[i] = __halves2bfloat162(__float2bfloat16(v0), __float2bfloat16(v1));
    }
#pragma unroll
    for (int o=16;o;o>>=1) bsum += __shfl_xor_sync(0xffffffffu, bsum, o);
    if (lane==0) g_cb[n] = bsum*scale;
    size_t off = (size_t)n*DIM + lane*8;
    *(uint4*)(g_Wh + off) = *(uint4*)h2;
}

/* ------------- 4. tensor-core KV GEMM (plain bf16) ---------------------- */
/* C[262144,512] = A @ Wc^T ; BM=128 BN=128 BK=32, 4-stage cp.async,        */
/* 8 warps (4m x 2n), warp tile 32x64, smem stride 40 bf16                  */
#define LDSB 40
#define STG  20480   /* 2 arrays * 128*40*2 */
__global__ __launch_bounds__(256) void k_kvgemm_mma(){
    extern __shared__ __align__(16) char smem_raw[];
    const unsigned sbase = smem_u32(smem_raw);
    const int tid  = threadIdx.x;
    const int warp = tid>>5, lane = tid&31;
    const int m0 = blockIdx.y*128;
    const int n0 = blockIdx.x*128;
    const int wm = (warp&3)*32;
    const int wn = (warp>>2)*64;

    float acc[2][8][4];
#pragma unroll
    for (int i=0;i<2;i++)
#pragma unroll
        for (int j=0;j<8;j++)
#pragma unroll
            for (int c=0;c<4;c++) acc[i][j][c]=0.f;

    auto load_stage = [&](int st, int k0){
        unsigned base = sbase + st*STG;
        int row = tid>>2, seg = tid&3;
#pragma unroll
        for (int p=0;p<2;p++){
            int r = row + p*64;
            size_t ga = ((size_t)(m0+r))*DIM + k0 + seg*8;
            size_t gw = ((size_t)(n0+r))*DIM + k0 + seg*8;
            unsigned dst = base + (unsigned)(r*80 + seg*16);
            cp16(dst,          g_Ah + ga);
            cp16(dst + 10240,  g_Wh + gw);
        }
    };

#pragma unroll
    for (int s=0;s<3;s++){ load_stage(s, s*32); cp_commit(); }

#pragma unroll 1
    for (int kt=0; kt<8; kt++){
        if (kt < 6) cp_wait2();
        else if (kt == 6) cp_wait1();
        else cp_wait0();
        __syncthreads();
        if (kt < 5){ load_stage((kt+3)&3, (kt+3)*32); cp_commit(); }
        unsigned base = sbase + (kt&3)*STG;
#pragma unroll
        for (int ks=0; ks<32; ks+=16){
            unsigned ah[2][4];
#pragma unroll
            for (int mt=0;mt<2;mt++){
                unsigned addr = base + (unsigned)(((wm + mt*16 + (lane&15))*LDSB
                                         + ks + ((lane>>4)<<3))*2);
                ldm4(ah[mt][0],ah[mt][1],ah[mt][2],ah[mt][3], addr);
            }
            unsigned bh[4][4];
#pragma unroll
            for (int nt2=0;nt2<4;nt2++){
                unsigned addr = base + 10240u + (unsigned)(((wn + nt2*16 + (lane&15))*LDSB
                                         + ks + ((lane>>4)<<3))*2);
                ldm4(bh[nt2][0],bh[nt2][1],bh[nt2][2],bh[nt2][3], addr);
            }
#pragma unroll
            for (int mt=0;mt<2;mt++)
#pragma unroll
                for (int nt=0;nt<8;nt++){
                    int nt2 = nt>>1, pr = nt&1;
                    mma16816(acc[mt][nt], ah[mt], bh[nt2][pr], bh[nt2][pr+2]);
                }
        }
        __syncthreads();
    }

    /* epilogue: add folded bias, write bf16 to g_kb / g_vb */
    bool isk = (n0 < 256);
    __nv_bfloat16* Cb = isk ? g_kb : g_vb;
    int ncol0 = isk ? n0 : (n0 - 256);
#pragma unroll
    for (int mt=0;mt<2;mt++){
        int r = m0 + wm + mt*16 + (lane>>2);
#pragma unroll
        for (int nt=0;nt<8;nt++){
            int nl = wn + nt*8 + (lane&3)*2;
            int gn = n0 + nl;
            float bx = g_cb[gn], by = g_cb[gn+1];
            __nv_bfloat16* d0 = Cb + (((size_t)r)<<8) + ncol0 + nl;
            __nv_bfloat16* d1 = Cb + (((size_t)(r+8))<<8) + ncol0 + nl;
            *(__nv_bfloat162*)d0 = __halves2bfloat162(
                __float2bfloat16(acc[mt][nt][0]+bx), __float2bfloat16(acc[mt][nt][1]+by));
            *(__nv_bfloat162*)d1 = __halves2bfloat162(
                __float2bfloat16(acc[mt][nt][2]+bx), __float2bfloat16(acc[mt][nt][3]+by));
        }
    }
}

/* ---------------------- 5. q = LN(slots) @ Wq^T ------------------------- */
__global__ __launch_bounds__(256) void k_q(const float* __restrict__ Wq,
        const float* __restrict__ gsl, const float* __restrict__ bsl){
    int r = blockIdx.x, t = threadIdx.x;
    int warp = t>>5, lane = t&31;
    __shared__ float xs[256];
    __shared__ float rs_[8], rq_[8];
    __shared__ float mv[2];
    float x = g_slots[r*256 + t];
    float s = x, q = x*x;
#pragma unroll
    for (int o=16;o;o>>=1){
        s += __shfl_xor_sync(0xffffffffu, s, o);
        q += __shfl_xor_sync(0xffffffffu, q, o);
    }
    if (lane==0){ rs_[warp]=s; rq_[warp]=q; }
    __syncthreads();
    if (t==0){
        float S=0.f,Q=0.f;
#pragma unroll
        for (int w=0;w<8;w++){ S+=rs_[w]; Q+=rq_[w]; }
        float m = S*(1.0f/256.f);
        mv[0]=m; mv[1]=rsqrtf(Q*(1.0f/256.f)-m*m+LNEPS);
    }
    __syncthreads();
    xs[t] = (x - mv[0])*mv[1]*gsl[t] + bsl[t];
    __syncthreads();
    float acc = 0.f;
    const float4* w = (const float4*)(Wq + (size_t)t*256);
#pragma unroll 8
    for (int d=0; d<64; d++)
        acc += dot4_(w[d], *(const float4*)&xs[d*4]);
    g_q[r*256 + t] = acc;
}

/* ------- 6. logits + softmax(over 8 slots) + EPS + partial colsum ------- */
__global__ __launch_bounds__(256) void k_attn(){
    int b = blockIdx.y, chunk = blockIdx.x;
    int warp = threadIdx.x>>5, lane = threadIdx.x&31;
    __shared__ float cs_s[8][8];
    float qreg[8][8];
#pragma unroll
    for (int kk=0;kk<8;kk++)
#pragma unroll
        for (int j=0;j<8;j++)
            qreg[kk][j] = g_q[((b<<3)+kk)*256 + lane*8 + j];
    float csum[8];
#pragma unroll
    for (int kk=0;kk<8;kk++) csum[kk]=0.f;
    int n0 = chunk*512 + warp*64;
    for (int i=0;i<64;i++){
        size_t row = (size_t)(b*NTOK + n0 + i);
        uint4 raw = *(const uint4*)(g_kb + (row<<8) + lane*8);
        const __nv_bfloat162* kb2 = (const __nv_bfloat162*)&raw;
        float kf[8];
#pragma unroll
        for (int p=0;p<4;p++){
            float2 f = __bfloat1622float2(kb2[p]);
            kf[2*p] = f.x; kf[2*p+1] = f.y;
        }
        float lg[8];
#pragma unroll
        for (int kk=0;kk<8;kk++) lg[kk]=0.f;
#pragma unroll
        for (int j=0;j<8;j++){
#pragma unroll
            for (int kk=0;kk<8;kk++) lg[kk] += kf[j] * qreg[kk][j];
        }
#pragma unroll
        for (int kk=0;kk<8;kk++){
#pragma unroll
            for (int o=16;o;o>>=1)
                lg[kk] += __shfl_xor_sync(0xffffffffu, lg[kk], o);
        }
        if (lane==0){
            float m = lg[0];
#pragma unroll
            for (int kk=1;kk<8;kk++) m = fmaxf(m, lg[kk]);
            float e[8]; float ssum = 0.f;
#pragma unroll
            for (int kk=0;kk<8;kk++){ e[kk] = expf(lg[kk]-m); ssum += e[kk]; }
            float inv = 1.0f/ssum;
            float a[8];
#pragma unroll
            for (int kk=0;kk<8;kk++){ a[kk] = e[kk]*inv + EPSA; csum[kk] += a[kk]; }
            float* dst = g_attn + row*KSLOT;
            *(float4*)dst     = make_float4(a[0],a[1],a[2],a[3]);
            *(float4*)(dst+4) = make_float4(a[4],a[5],a[6],a[7]);
        }
    }
    if (lane==0){
#pragma unroll
        for (int kk=0;kk<8;kk++) cs_s[warp][kk] = csum[kk];
    }
    __syncthreads();
    if (threadIdx.x < 8){
        float s = 0.f;
#pragma unroll
        for (int w=0;w<8;w++) s += cs_s[w][threadIdx.x];
        g_cspart[(b*NCHUNK + chunk)*KSLOT + threadIdx.x] = s;
    }
}

/* ------------- 7. partial updates: per-chunk attn^T @ v ---------------- */
/* 256 threads: c = t&127 owns dims (2c,2c+1), h = t>>7 token parity       */
__global__ __launch_bounds__(256) void k_updpart(){
    int b = blockIdx.y, chunk = blockIdx.x, t = threadIdx.x;
    int h = t>>7, c = t&127;
    __shared__ float4 am[512][2];
    __shared__ float2 red[8][128];
    const float4* src = (const float4*)(g_attn + ((size_t)(b*NTOK + chunk*512))*KSLOT);
    for (int i=t; i<1024; i+=256) ((float4*)am)[i] = src[i];
    __syncthreads();
    float2 acc[8];
#pragma unroll
    for (int kk=0;kk<8;kk++) acc[kk]=make_float2(0.f,0.f);
    size_t vbase = ((size_t)(b*NTOK + chunk*512))<<8;
#pragma unroll 4
    for (int n2=0;n2<512;n2+=2){
        int n = n2 + h;
        __nv_bfloat162 v2 = *(const __nv_bfloat162*)(g_vb + vbase + ((size_t)n<<8) + c*2);
        float2 vv = __bfloat1622float2(v2);
        float4 a0 = am[n][0], a1 = am[n][1];
        acc[0].x += a0.x*vv.x; acc[0].y += a0.x*vv.y;
        acc[1].x += a0.y*vv.x; acc[1].y += a0.y*vv.y;
        acc[2].x += a0.z*vv.x; acc[2].y += a0.z*vv.y;
        acc[3].x += a0.w*vv.x; acc[3].y += a0.w*vv.y;
        acc[4].x += a1.x*vv.x; acc[4].y += a1.x*vv.y;
        acc[5].x += a1.y*vv.x; acc[5].y += a1.y*vv.y;
        acc[6].x += a1.z*vv.x; acc[6].y += a1.z*vv.y;
        acc[7].x += a1.w*vv.x; acc[7].y += a1.w*vv.y;
    }
    if (h==1){
#pragma unroll
        for (int kk=0;kk<8;kk++) red[kk][c] = acc[kk];
    }
    __syncthreads();
    if (h==0){
#pragma unroll
        for (int kk=0;kk<8;kk++){
            float2 r2 = red[kk][c];
            float2 o = make_float2(acc[kk].x + r2.x, acc[kk].y + r2.y);
            *(float2*)(g_updpart + (((size_t)chunk*BATCH + b)*KSLOT + kk)*256 + 2*c) = o;
        }
    }
}

/* ------------- 8. reduce partials, divide by colsum -------------------- */
__global__ void k_updreduce(){
    int i = blockIdx.x*256 + threadIdx.x;   /* 131072 */
    int s  = i & 255;
    int bk = i >> 8;
    int b  = bk >> 3;
    int kk = bk & 7;
    float cs = 0.f;
#pragma unroll
    for (int c=0;c<NCHUNK;c++) cs += g_cspart[(b*NCHUNK + c)*KSLOT + kk];
    float sum = 0.f;
#pragma unroll
    for (int c=0;c<NCHUNK;c++)
        sum += g_updpart[(((size_t)c*BATCH + b)*KSLOT + kk)*256 + s];
    g_upd[i] = sum / cs;
}

/* ------------- 9. GRU cell + optional MLP residual --------------------- */
__global__ __launch_bounds__(256) void k_gru(
        const float* __restrict__ Wih, const float* __restrict__ Whh,
        const float* __restrict__ bih, const float* __restrict__ bhh,
        const float* __restrict__ W1,  const float* __restrict__ b1,
        const float* __restrict__ W2,  const float* __restrict__ b2,
        const float* __restrict__ gm,  const float* __restrict__ bm,
        int do_mlp, float* __restrict__ out){
    int t = threadIdx.x;
    int r0 = blockIdx.x * 4;
    __shared__ float Xs[4][256];
    __shared__ float Hs[4][256];
    __shared__ float Hm[4][512];
    __shared__ float mred[4][2];
    for (int i=t; i<1024; i+=256){
        ((float*)Xs)[i] = g_upd  [r0*256 + i];
        ((float*)Hs)[i] = g_slots[r0*256 + i];
    }
    __syncthreads();

    float gi_[3][4], gh_[3][4];
#pragma unroll
    for (int g=0; g<3; g++){
        float ai[4]={0,0,0,0}, ah[4]={0,0,0,0};
        const float4* wi = (const float4*)(Wih + ((size_t)((g<<8)+t))*256);
        const float4* wh = (const float4*)(Whh + ((size_t)((g<<8)+t))*256);
#pragma unroll 4
        for (int d=0; d<64; d++){
            float4 a = wi[d], c = wh[d];
#pragma unroll
            for (int r=0;r<4;r++){
                float4 xv = *(const float4*)&Xs[r][d<<2];
                float4 hv = *(const float4*)&Hs[r][d<<2];
                ai[r] += a.x*xv.x + a.y*xv.y + a.z*xv.z + a.w*xv.w;
                ah[r] += c.x*hv.x + c.y*hv.y + c.z*hv.z + c.w*hv.w;
            }
        }
        float bi = bih[(g<<8)+t], bh = bhh[(g<<8)+t];
#pragma unroll
        for (int r=0;r<4;r++){ gi_[g][r] = ai[r]+bi; gh_[g][r] = ah[r]+bh; }
    }
    __syncthreads();

    float newv[4];
#pragma unroll
    for (int r=0;r<4;r++){
        float h  = Hs[r][t];
        float rr = sigmoidf_(gi_[0][r] + gh_[0][r]);
        float zz = sigmoidf_(gi_[1][r] + gh_[1][r]);
        float nn = tanhf(gi_[2][r] + rr*gh_[2][r]);
        newv[r] = (1.0f - zz)*nn + zz*h;
    }
#pragma unroll
    for (int r=0;r<4;r++) Xs[r][t] = newv[r];

    if (!do_mlp){
#pragma unroll
        for (int r=0;r<4;r++){
            g_slots[(r0+r)*256 + t] = newv[r];
            if (out) out[(r0+r)*256 + t] = newv[r];
        }
        return;
    }
    __syncthreads();
    int warp = t>>5, lane = t&31;
    if (warp < 4){
        float s=0.f, q=0.f;
#pragma unroll
        for (int j=0;j<8;j++){
            float xv = Xs[warp][lane + (j<<5)];
            s += xv; q += xv*xv;
        }
#pragma unroll
        for (int o=16;o;o>>=1){
            s += __shfl_xor_sync(0xffffffffu, s, o);
            q += __shfl_xor_sync(0xffffffffu, q, o);
        }
        if (lane==0){
            float m = s*(1.0f/256.f);
            mred[warp][0] = m;
            mred[warp][1] = rsqrtf(q*(1.0f/256.f) - m*m + LNEPS);
        }
    }
    __syncthreads();
    float gmt = gm[t], bmt = bm[t];
#pragma unroll
    for (int r=0;r<4;r++)
        Hs[r][t] = (Xs[r][t] - mred[r][0])*mred[r][1]*gmt + bmt;
    __syncthreads();
#pragma unroll
    for (int hblk=0; hblk<2; hblk++){
        int ho = t + (hblk<<8);
        float acc[4]={0,0,0,0};
        const float4* w = (const float4*)(W1 + (size_t)ho*256);
#pragma unroll 4
        for (int d=0; d<64; d++){
            float4 a = w[d];
#pragma unroll
            for (int r=0;r<4;r++)
                acc[r] += dot4_(a, *(const float4*)&Hs[r][d<<2]);
        }
        float bb = b1[ho];
#pragma unroll
        for (int r=0;r<4;r++) Hm[r][ho] = fmaxf(acc[r]+bb, 0.f);
    }
    __syncthreads();
    {
        float acc[4]={0,0,0,0};
        const float4* w = (const float4*)(W2 + (size_t)t*512);
#pragma unroll 4
        for (int j=0; j<128; j++){
            float4 a = w[j];
#pragma unroll
            for (int r=0;r<4;r++)
                acc[r] += dot4_(a, *(const float4*)&Hm[r][j<<2]);
        }
        float bb = b2[t];
#pragma unroll
        for (int r=0;r<4;r++)
            g_slots[(r0+r)*256 + t] = Xs[r][t] + acc[r] + bb;
    }
}

/* ----------------------------- launcher -------------------------------- */
extern "C" void kernel_launch(void* const* d_in, const int* in_sizes, int n_in,
                              void* d_out, int out_size){
    (void)in_sizes; (void)n_in; (void)out_size;
    const float* inputs = (const float*)d_in[0];
    const float* noise  = (const float*)d_in[1];
    const float* mu     = (const float*)d_in[2];
    const float* lsig   = (const float*)d_in[3];
    const float* gin    = (const float*)d_in[4];
    const float* bin    = (const float*)d_in[5];
    const float* gsl    = (const float*)d_in[6];
    const float* bsl    = (const float*)d_in[7];
    const float* gm     = (const float*)d_in[8];
    const float* bm     = (const float*)d_in[9];
    const float* Wq     = (const float*)d_in[10];
    const float* Wk     = (const float*)d_in[11];
    const float* Wv     = (const float*)d_in[12];
    const float* Wih    = (const float*)d_in[13];
    const float* Whh    = (const float*)d_in[14];
    const float* bih    = (const float*)d_in[15];
    const float* bhh    = (const float*)d_in[16];
    const float* W1     = (const float*)d_in[17];
    const float* b1     = (const float*)d_in[18];
    const float* W2     = (const float*)d_in[19];
    const float* b2     = (const float*)d_in[20];
    float* out = (float*)d_out;

    cudaFuncSetAttribute(k_kvgemm_mma,
                         cudaFuncAttributeMaxDynamicSharedMemorySize, 4*STG);

    k_init_slots<<<512, 256>>>(noise, mu, lsig);
    k_prep_a<<<NROWS/8, 256>>>(inputs);
    k_prep_w<<<64, 256>>>(Wk, Wv, gin, bin);
    k_kvgemm_mma<<<dim3(4, NROWS/128), 256, 4*STG>>>();
    for (int it=0; it<3; it++){
        k_q<<<BATCH*KSLOT, 256>>>(Wq, gsl, bsl);
        k_attn<<<dim3(NCHUNK, BATCH), 256>>>();
        k_updpart<<<dim3(NCHUNK, BATCH), 256>>>();
        k_updreduce<<<512, 256>>>();
        k_gru<<<128, 256>>>(Wih, Whh, bih, bhh, W1, b1, W2, b2, gm, bm,
                            (it < 2) ? 1 : 0, (it == 2) ? out : nullptr);
    }
}

// round 7
// speedup vs baseline: 3.9855x; 1.7897x over previous
#include <cuda_runtime.h>
#include <cuda_bf16.h>
#include <math.h>
#include <stddef.h>

#define BATCH  64
#define NTOK   4096
#define DIM    256
#define SDIM   256
#define KSLOT  8
#define EPSA   1e-8f
#define LNEPS  1e-5f
#define NROWS  (BATCH*NTOK)       /* 262144 */
#define NCHUNK 8                  /* 512 tokens per chunk */

/* ------------- scratch (device globals; no allocation allowed) ---------- */
__device__ __align__(16) __nv_bfloat16 g_Ah[(size_t)NROWS*DIM];    /* 128 MB */
__device__ __align__(16) __nv_bfloat16 g_WkT[256*256];  /* WkT[d][s]=Wk[s,d]*g[d]/16 */
__device__ __align__(16) __nv_bfloat16 g_Wvf[256*256];  /* Wvf[s][d]=Wv[s,d]*g[d]   */
__device__ __align__(16) float g_cbk[256];
__device__ __align__(16) float g_cbv[256];
__device__ __align__(16) float g_slots[BATCH*KSLOT*SDIM];
__device__ __align__(16) __nv_bfloat16 g_qkb[BATCH*KSLOT*DIM];
__device__ __align__(16) float g_qk0[BATCH*KSLOT];
__device__ __align__(16) float g_updpart[NCHUNK*BATCH*KSLOT*DIM];  /* 4 MB */
__device__ __align__(16) float g_cspart[BATCH*NCHUNK*KSLOT];

__device__ __forceinline__ float sigmoidf_(float x){ return 1.0f/(1.0f + expf(-x)); }
__device__ __forceinline__ float dot4_(float4 a, float4 b){
    return a.x*b.x + a.y*b.y + a.z*b.z + a.w*b.w;
}

/* ----------------------- PTX helpers ----------------------------------- */
__device__ __forceinline__ unsigned smem_u32(const void* p){
    return (unsigned)__cvta_generic_to_shared(p);
}
__device__ __forceinline__ void cp16(unsigned dst, const void* src){
    asm volatile("cp.async.cg.shared.global [%0],[%1],16;\n"::"r"(dst),"l"(src));
}
__device__ __forceinline__ void cp_commit(){ asm volatile("cp.async.commit_group;\n"::); }
__device__ __forceinline__ void cp_wait1(){ asm volatile("cp.async.wait_group 1;\n"::); }
__device__ __forceinline__ void cp_wait0(){ asm volatile("cp.async.wait_group 0;\n"::); }
__device__ __forceinline__ void ldm4(unsigned&r0,unsigned&r1,unsigned&r2,unsigned&r3,unsigned a){
    asm volatile("ldmatrix.sync.aligned.m8n8.x4.shared.b16 {%0,%1,%2,%3},[%4];\n"
        :"=r"(r0),"=r"(r1),"=r"(r2),"=r"(r3):"r"(a));
}
__device__ __forceinline__ void mma16816(float* c, const unsigned* a, unsigned b0, unsigned b1){
    asm volatile("mma.sync.aligned.m16n8k16.row.col.f32.bf16.bf16.f32 "
        "{%0,%1,%2,%3},{%4,%5,%6,%7},{%8,%9},{%0,%1,%2,%3};\n"
        :"+f"(c[0]),"+f"(c[1]),"+f"(c[2]),"+f"(c[3])
        :"r"(a[0]),"r"(a[1]),"r"(a[2]),"r"(a[3]),"r"(b0),"r"(b1));
}

/* ---------------------- 1. slots = mu + exp(ls)*noise ------------------- */
__global__ void k_init_slots(const float* __restrict__ noise,
                             const float* __restrict__ mu,
                             const float* __restrict__ lsig){
    int i = blockIdx.x*256 + threadIdx.x;
    int s = i & (SDIM-1);
    g_slots[i] = mu[s] + expf(lsig[s]) * noise[i];
}

/* ------------- 2. LN(inputs, no affine) -> bf16 ------------------------ */
__global__ __launch_bounds__(256) void k_prep_a(const float* __restrict__ inp){
    int row  = blockIdx.x*8 + (threadIdx.x >> 5);
    int lane = threadIdx.x & 31;
    const float4* p = (const float4*)(inp + (size_t)row*DIM);
    float4 a = p[lane*2], b = p[lane*2+1];
    float x[8] = {a.x,a.y,a.z,a.w,b.x,b.y,b.z,b.w};
    float s = 0.f, q = 0.f;
#pragma unroll
    for (int i=0;i<8;i++){ s += x[i]; q += x[i]*x[i]; }
#pragma unroll
    for (int o=16;o;o>>=1){
        s += __shfl_xor_sync(0xffffffffu, s, o);
        q += __shfl_xor_sync(0xffffffffu, q, o);
    }
    float m = s*(1.0f/DIM);
    float rstd = rsqrtf(q*(1.0f/DIM) - m*m + LNEPS);
    __nv_bfloat162 h2[4];
#pragma unroll
    for (int i=0;i<4;i++){
        h2[i] = __halves2bfloat162(__float2bfloat16((x[2*i]-m)*rstd),
                                   __float2bfloat16((x[2*i+1]-m)*rstd));
    }
    size_t off = (size_t)row*DIM + lane*8;
    *(uint4*)(g_Ah + off) = *(uint4*)h2;
}

/* ------------- 3. weight prep: fold gamma/beta/scale -------------------- */
/* grid 256 (block = s), 256 threads (thread = d)                           */
__global__ __launch_bounds__(256) void k_prep_w(const float* __restrict__ Wk,
        const float* __restrict__ Wv, const float* __restrict__ gin,
        const float* __restrict__ bin){
    __shared__ float rk[8], rv[8];
    int s = blockIdx.x, d = threadIdx.x;
    int w = d>>5, l = d&31;
    float gk = gin[d], bt = bin[d];
    float wk = Wk[s*256+d], wv = Wv[s*256+d];
    g_WkT[d*256+s] = __float2bfloat16(wk*gk*0.0625f);
    g_Wvf[s*256+d] = __float2bfloat16(wv*gk);
    float pk = wk*bt, pv = wv*bt;
#pragma unroll
    for (int o=16;o;o>>=1){
        pk += __shfl_xor_sync(0xffffffffu, pk, o);
        pv += __shfl_xor_sync(0xffffffffu, pv, o);
    }
    if (l==0){ rk[w]=pk; rv[w]=pv; }
    __syncthreads();
    if (d==0){
        float sk=0.f, sv=0.f;
#pragma unroll
        for (int i=0;i<8;i++){ sk+=rk[i]; sv+=rv[i]; }
        g_cbk[s] = sk*0.0625f;
        g_cbv[s] = sv;
    }
}

/* ------------- 4. q = LN(slots)@Wq^T ; qk = q@Wkf ; qk0 ----------------- */
/* grid 64 (batch), 256 threads. warp w does LN of slot w.                  */
__global__ __launch_bounds__(256) void k_qk(const float* __restrict__ Wq,
        const float* __restrict__ gsl, const float* __restrict__ bsl){
    __shared__ float xs[8][256];
    __shared__ float qs[8][256];
    __shared__ float redp[8][8];
    int b = blockIdx.x, t = threadIdx.x, w = t>>5, l = t&31;
    /* LN of slot row w */
    {
        const float4* sr = (const float4*)(g_slots + (b*8+w)*256);
        float4 a = sr[l*2], c = sr[l*2+1];
        float v[8] = {a.x,a.y,a.z,a.w,c.x,c.y,c.z,c.w};
        float s=0.f, q=0.f;
#pragma unroll
        for (int i=0;i<8;i++){ s+=v[i]; q+=v[i]*v[i]; }
#pragma unroll
        for (int o=16;o;o>>=1){
            s += __shfl_xor_sync(0xffffffffu, s, o);
            q += __shfl_xor_sync(0xffffffffu, q, o);
        }
        float m = s*(1.0f/256.f);
        float rstd = rsqrtf(q*(1.0f/256.f)-m*m+LNEPS);
#pragma unroll
        for (int i=0;i<8;i++)
            xs[w][l*8+i] = (v[i]-m)*rstd*gsl[l*8+i] + bsl[l*8+i];
    }
    __syncthreads();
    /* q[k][t] */
    float q8[8] = {0,0,0,0,0,0,0,0};
    {
        const float4* wq = (const float4*)(Wq + (size_t)t*256);
#pragma unroll 8
        for (int d4=0; d4<64; d4++){
            float4 wv4 = wq[d4];
#pragma unroll
            for (int k=0;k<8;k++)
                q8[k] += dot4_(wv4, *(const float4*)&xs[k][d4*4]);
        }
    }
    /* qk0 partials */
    {
        float cbt = g_cbk[t];
        float p[8];
#pragma unroll
        for (int k=0;k<8;k++) p[k] = q8[k]*cbt;
#pragma unroll
        for (int k=0;k<8;k++)
#pragma unroll
            for (int o=16;o;o>>=1) p[k] += __shfl_xor_sync(0xffffffffu, p[k], o);
        if (l==0)
#pragma unroll
            for (int k=0;k<8;k++) redp[w][k] = p[k];
    }
#pragma unroll
    for (int k=0;k<8;k++) qs[k][t] = q8[k];
    __syncthreads();
    if (t<8){
        float s=0.f;
#pragma unroll
        for (int i=0;i<8;i++) s += redp[i][t];
        g_qk0[b*8+t] = s;
    }
    /* qk[k][d=t] = sum_s qs[k][s]*WkT[t][s] */
    float o8[8] = {0,0,0,0,0,0,0,0};
    {
        const uint4* wkt = (const uint4*)(g_WkT + (size_t)t*256);
#pragma unroll 4
        for (int s8=0; s8<32; s8++){
            uint4 raw = wkt[s8];
            const __nv_bfloat162* p2 = (const __nv_bfloat162*)&raw;
#pragma unroll
            for (int j2=0;j2<4;j2++){
                float2 f = __bfloat1622float2(p2[j2]);
#pragma unroll
                for (int k=0;k<8;k++){
                    o8[k] += qs[k][s8*8+2*j2]  *f.x;
                    o8[k] += qs[k][s8*8+2*j2+1]*f.y;
                }
            }
        }
    }
#pragma unroll
    for (int k=0;k<8;k++)
        g_qkb[(b*8+k)*256 + t] = __float2bfloat16(o8[k]);
}

/* ------------- 5. fused: logits(MMA) + softmax + ux accumulation -------- */
/* grid (8 chunks, 64 batches), 256 thr, 512 tokens/block, 4 subtiles x128 */
#define LDSB2 264                        /* bf16 elems per padded row */
#define XTB   (128*LDSB2*2)              /* 67584 B per x' buffer */
#define SMEMB (2*XTB + 4096 + 8192 + 256 + 32)
__global__ __launch_bounds__(256) void k_fused(){
    extern __shared__ __align__(16) char sm[];
    float*  attn_s = (float*)(sm + 2*XTB);            /* [128][8]        */
    float2* red    = (float2*)(sm + 2*XTB + 4096);    /* [8][128]        */
    float*  csum_s = (float*)(sm + 2*XTB + 4096 + 8192); /* [8 warps][8] */
    float*  qk0s   = csum_s + 64;
    const unsigned sb = smem_u32(sm);
    const int b = blockIdx.y, chunk = blockIdx.x;
    const int t = threadIdx.x, w = t>>5, l = t&31;
    const int h = t>>7, c = t&127;
    const int col0 = (l&3)*2;

    /* B fragments: qk for this batch, resident in registers */
    unsigned bf[16][2];
    {
        const __nv_bfloat16* qkb = g_qkb + ((size_t)b*8 + (l>>2))*256 + col0;
#pragma unroll
        for (int s16=0;s16<16;s16++){
            bf[s16][0] = *(const unsigned*)(qkb + s16*16);
            bf[s16][1] = *(const unsigned*)(qkb + s16*16 + 8);
        }
    }
    if (t<8) qk0s[t] = g_qk0[b*8+t];

    float cs0=0.f, cs1=0.f;
    float ua[16];
#pragma unroll
    for (int i=0;i<16;i++) ua[i]=0.f;

    const size_t grow0 = (size_t)(b*NTOK + chunk*512);
    auto load_x = [&](int buf, int tok0){
        unsigned dstb = sb + buf*XTB;
        int rr = t>>1;
        int sg0 = (t&1)*16;
#pragma unroll
        for (int j=0;j<16;j++){
            int seg = sg0 + j;
            cp16(dstb + (unsigned)(rr*528 + seg*16),
                 g_Ah + (grow0 + tok0 + rr)*DIM + seg*8);
        }
    };
    load_x(0, 0); cp_commit();

#pragma unroll 1
    for (int st=0; st<4; st++){
        __syncthreads();                       /* phase2(st-1) done before reuse */
        if (st<3){ load_x((st+1)&1, (st+1)*128); cp_commit(); cp_wait1(); }
        else cp_wait0();
        __syncthreads();
        unsigned xb = sb + (st&1)*XTB;
        /* phase 1: warp w -> tokens [w*16, w*16+16) */
        float cacc[4] = {0.f,0.f,0.f,0.f};
#pragma unroll
        for (int s16=0;s16<16;s16++){
            unsigned a[4];
            unsigned addr = xb + (unsigned)(((w*16 + (l&15))*LDSB2
                               + s16*16 + ((l>>4)<<3))*2);
            ldm4(a[0],a[1],a[2],a[3], addr);
            mma16816(cacc, a, bf[s16][0], bf[s16][1]);
        }
        cacc[0] += qk0s[col0]; cacc[1] += qk0s[col0+1];
        cacc[2] += qk0s[col0]; cacc[3] += qk0s[col0+1];
        /* softmax over 8 slots: quad reduction (lanes sharing l>>2) */
        float m0 = fmaxf(cacc[0],cacc[1]), m1 = fmaxf(cacc[2],cacc[3]);
        m0 = fmaxf(m0, __shfl_xor_sync(0xffffffffu, m0, 1));
        m1 = fmaxf(m1, __shfl_xor_sync(0xffffffffu, m1, 1));
        m0 = fmaxf(m0, __shfl_xor_sync(0xffffffffu, m0, 2));
        m1 = fmaxf(m1, __shfl_xor_sync(0xffffffffu, m1, 2));
        float e0 = expf(cacc[0]-m0), e1 = expf(cacc[1]-m0);
        float e2 = expf(cacc[2]-m1), e3 = expf(cacc[3]-m1);
        float s0 = e0+e1, s1 = e2+e3;
        s0 += __shfl_xor_sync(0xffffffffu, s0, 1);
        s1 += __shfl_xor_sync(0xffffffffu, s1, 1);
        s0 += __shfl_xor_sync(0xffffffffu, s0, 2);
        s1 += __shfl_xor_sync(0xffffffffu, s1, 2);
        float i0 = 1.0f/s0, i1 = 1.0f/s1;
        float a0 = e0*i0+EPSA, a1 = e1*i0+EPSA;
        float a2 = e2*i1+EPSA, a3 = e3*i1+EPSA;
        cs0 += a0+a2; cs1 += a1+a3;
        int row = w*16 + (l>>2);
        *(float2*)&attn_s[row*8 + col0]     = make_float2(a0,a1);
        *(float2*)&attn_s[(row+8)*8 + col0] = make_float2(a2,a3);
        __syncthreads();
        /* phase 2: ux accumulation; thread owns dims (2c,2c+1), parity h */
        const char* xgen = sm + (st&1)*XTB;
#pragma unroll 4
        for (int i=0;i<64;i++){
            int n = 2*i + h;
            float2 xv = __bfloat1622float2(
                *(const __nv_bfloat162*)(xgen + n*528 + 4*c));
            float4 p0 = *(const float4*)&attn_s[n*8];
            float4 p1 = *(const float4*)&attn_s[n*8+4];
            ua[0]  += p0.x*xv.x; ua[1]  += p0.x*xv.y;
            ua[2]  += p0.y*xv.x; ua[3]  += p0.y*xv.y;
            ua[4]  += p0.z*xv.x; ua[5]  += p0.z*xv.y;
            ua[6]  += p0.w*xv.x; ua[7]  += p0.w*xv.y;
            ua[8]  += p1.x*xv.x; ua[9]  += p1.x*xv.y;
            ua[10] += p1.y*xv.x; ua[11] += p1.y*xv.y;
            ua[12] += p1.z*xv.x; ua[13] += p1.z*xv.y;
            ua[14] += p1.w*xv.x; ua[15] += p1.w*xv.y;
        }
    }
    /* colsum reduction */
    cs0 += __shfl_xor_sync(0xffffffffu, cs0, 4);
    cs1 += __shfl_xor_sync(0xffffffffu, cs1, 4);
    cs0 += __shfl_xor_sync(0xffffffffu, cs0, 8);
    cs1 += __shfl_xor_sync(0xffffffffu, cs1, 8);
    cs0 += __shfl_xor_sync(0xffffffffu, cs0, 16);
    cs1 += __shfl_xor_sync(0xffffffffu, cs1, 16);
    if (l<4){ csum_s[w*8 + col0] = cs0; csum_s[w*8 + col0 + 1] = cs1; }
    /* ux parity exchange */
    if (h==1){
#pragma unroll
        for (int k=0;k<8;k++) red[k*128+c] = make_float2(ua[2*k],ua[2*k+1]);
    }
    __syncthreads();
    if (t<8){
        float s=0.f;
#pragma unroll
        for (int ww=0;ww<8;ww++) s += csum_s[ww*8+t];
        g_cspart[(b*NCHUNK + chunk)*KSLOT + t] = s;
    }
    if (h==0){
#pragma unroll
        for (int k=0;k<8;k++){
            float2 r2 = red[k*128+c];
            *(float2*)(g_updpart + (((size_t)chunk*BATCH*KSLOT) + b*8 + k)*256 + 2*c)
                = make_float2(ua[2*k]+r2.x, ua[2*k+1]+r2.y);
        }
    }
}

/* ------------- 6. finalize updates + GRU + optional MLP ----------------- */
/* grid 128, 4 (b,k)-rows per block */
__global__ __launch_bounds__(256) void k_gru(
        const float* __restrict__ Wih, const float* __restrict__ Whh,
        const float* __restrict__ bih, const float* __restrict__ bhh,
        const float* __restrict__ W1,  const float* __restrict__ b1,
        const float* __restrict__ W2,  const float* __restrict__ b2,
        const float* __restrict__ gm,  const float* __restrict__ bm,
        int do_mlp, float* __restrict__ out){
    int t = threadIdx.x;
    int r0 = blockIdx.x * 4;
    __shared__ float Us[4][256];
    __shared__ float Xs[4][256];
    __shared__ float Hs[4][256];
    __shared__ float Hm[4][512];
    __shared__ float mred[4][2];
    __shared__ float csum[4];
    /* ux chunk-reduce + slots load */
#pragma unroll
    for (int r=0;r<4;r++){
        int gr = r0+r;
        float s=0.f;
#pragma unroll
        for (int cc=0;cc<NCHUNK;cc++)
            s += g_updpart[(((size_t)cc*BATCH*KSLOT) + gr)*256 + t];
        Us[r][t] = s;
        Hs[r][t] = g_slots[gr*256 + t];
    }
    if (t<4){
        int gr = r0+t, bb = gr>>3, kk = gr&7;
        float cs=0.f;
#pragma unroll
        for (int cc=0;cc<NCHUNK;cc++) cs += g_cspart[(bb*NCHUNK+cc)*KSLOT + kk];
        csum[t] = cs;
    }
    __syncthreads();
    /* updates[r][s=t] = (Us[r]·Wvf[t]) / csum[r] + cbv[t] */
    {
        float acc[4] = {0,0,0,0};
        const uint4* wv = (const uint4*)(g_Wvf + (size_t)t*256);
#pragma unroll 4
        for (int s8=0;s8<32;s8++){
            uint4 raw = wv[s8];
            const __nv_bfloat162* p2 = (const __nv_bfloat162*)&raw;
#pragma unroll
            for (int j2=0;j2<4;j2++){
                float2 f = __bfloat1622float2(p2[j2]);
#pragma unroll
                for (int r=0;r<4;r++){
                    acc[r] += Us[r][s8*8+2*j2]  *f.x;
                    acc[r] += Us[r][s8*8+2*j2+1]*f.y;
                }
            }
        }
        float cbt = g_cbv[t];
#pragma unroll
        for (int r=0;r<4;r++) Xs[r][t] = acc[r]/csum[r] + cbt;
    }
    __syncthreads();

    float gi_[3][4], gh_[3][4];
#pragma unroll
    for (int g=0; g<3; g++){
        float ai[4]={0,0,0,0}, ah[4]={0,0,0,0};
        const float4* wi = (const float4*)(Wih + ((size_t)((g<<8)+t))*256);
        const float4* wh = (const float4*)(Whh + ((size_t)((g<<8)+t))*256);
#pragma unroll 4
        for (int d=0; d<64; d++){
            float4 a = wi[d], cc = wh[d];
#pragma unroll
            for (int r=0;r<4;r++){
                float4 xv = *(const float4*)&Xs[r][d<<2];
                float4 hv = *(const float4*)&Hs[r][d<<2];
                ai[r] += a.x*xv.x + a.y*xv.y + a.z*xv.z + a.w*xv.w;
                ah[r] += cc.x*hv.x + cc.y*hv.y + cc.z*hv.z + cc.w*hv.w;
            }
        }
        float bi = bih[(g<<8)+t], bh = bhh[(g<<8)+t];
#pragma unroll
        for (int r=0;r<4;r++){ gi_[g][r] = ai[r]+bi; gh_[g][r] = ah[r]+bh; }
    }
    __syncthreads();

    float newv[4];
#pragma unroll
    for (int r=0;r<4;r++){
        float hh = Hs[r][t];
        float rr = sigmoidf_(gi_[0][r] + gh_[0][r]);
        float zz = sigmoidf_(gi_[1][r] + gh_[1][r]);
        float nn = tanhf(gi_[2][r] + rr*gh_[2][r]);
        newv[r] = (1.0f - zz)*nn + zz*hh;
    }
#pragma unroll
    for (int r=0;r<4;r++) Xs[r][t] = newv[r];

    if (!do_mlp){
#pragma unroll
        for (int r=0;r<4;r++){
            g_slots[(r0+r)*256 + t] = newv[r];
            if (out) out[(r0+r)*256 + t] = newv[r];
        }
        return;
    }
    __syncthreads();
    int warp = t>>5, lane = t&31;
    if (warp < 4){
        float s=0.f, q=0.f;
#pragma unroll
        for (int j=0;j<8;j++){
            float xv = Xs[warp][lane + (j<<5)];
            s += xv; q += xv*xv;
        }
#pragma unroll
        for (int o=16;o;o>>=1){
            s += __shfl_xor_sync(0xffffffffu, s, o);
            q += __shfl_xor_sync(0xffffffffu, q, o);
        }
        if (lane==0){
            float m = s*(1.0f/256.f);
            mred[warp][0] = m;
            mred[warp][1] = rsqrtf(q*(1.0f/256.f) - m*m + LNEPS);
        }
    }
    __syncthreads();
    float gmt = gm[t], bmt = bm[t];
#pragma unroll
    for (int r=0;r<4;r++)
        Hs[r][t] = (Xs[r][t] - mred[r][0])*mred[r][1]*gmt + bmt;
    __syncthreads();
#pragma unroll
    for (int hblk=0; hblk<2; hblk++){
        int ho = t + (hblk<<8);
        float acc[4]={0,0,0,0};
        const float4* wp = (const float4*)(W1 + (size_t)ho*256);
#pragma unroll 4
        for (int d=0; d<64; d++){
            float4 a = wp[d];
#pragma unroll
            for (int r=0;r<4;r++)
                acc[r] += dot4_(a, *(const float4*)&Hs[r][d<<2]);
        }
        float bb = b1[ho];
#pragma unroll
        for (int r=0;r<4;r++) Hm[r][ho] = fmaxf(acc[r]+bb, 0.f);
    }
    __syncthreads();
    {
        float acc[4]={0,0,0,0};
        const float4* wp = (const float4*)(W2 + (size_t)t*512);
#pragma unroll 4
        for (int j=0; j<128; j++){
            float4 a = wp[j];
#pragma unroll
            for (int r=0;r<4;r++)
                acc[r] += dot4_(a, *(const float4*)&Hm[r][j<<2]);
        }
        float bb = b2[t];
#pragma unroll
        for (int r=0;r<4;r++)
            g_slots[(r0+r)*256 + t] = Xs[r][t] + acc[r] + bb;
    }
}

/* ----------------------------- launcher -------------------------------- */
extern "C" void kernel_launch(void* const* d_in, const int* in_sizes, int n_in,
                              void* d_out, int out_size){
    (void)in_sizes; (void)n_in; (void)out_size;
    const float* inputs = (const float*)d_in[0];
    const float* noise  = (const float*)d_in[1];
    const float* mu     = (const float*)d_in[2];
    const float* lsig   = (const float*)d_in[3];
    const float* gin    = (const float*)d_in[4];
    const float* bin    = (const float*)d_in[5];
    const float* gsl    = (const float*)d_in[6];
    const float* bsl    = (const float*)d_in[7];
    const float* gm     = (const float*)d_in[8];
    const float* bm     = (const float*)d_in[9];
    const float* Wq     = (const float*)d_in[10];
    const float* Wk     = (const float*)d_in[11];
    const float* Wv     = (const float*)d_in[12];
    const float* Wih    = (const float*)d_in[13];
    const float* Whh    = (const float*)d_in[14];
    const float* bih    = (const float*)d_in[15];
    const float* bhh    = (const float*)d_in[16];
    const float* W1     = (const float*)d_in[17];
    const float* b1     = (const float*)d_in[18];
    const float* W2     = (const float*)d_in[19];
    const float* b2     = (const float*)d_in[20];
    float* out = (float*)d_out;

    cudaFuncSetAttribute(k_fused,
                         cudaFuncAttributeMaxDynamicSharedMemorySize, SMEMB);

    k_init_slots<<<512, 256>>>(noise, mu, lsig);
    k_prep_a<<<NROWS/8, 256>>>(inputs);
    k_prep_w<<<256, 256>>>(Wk, Wv, gin, bin);
    for (int it=0; it<3; it++){
        k_qk<<<BATCH, 256>>>(Wq, gsl, bsl);
        k_fused<<<dim3(NCHUNK, BATCH), 256, SMEMB>>>();
        k_gru<<<128, 256>>>(Wih, Whh, bih, bhh, W1, b1, W2, b2, gm, bm,
                            (it < 2) ? 1 : 0, (it == 2) ? out : nullptr);
    }
}

// round 8
// speedup vs baseline: 4.3864x; 1.1006x over previous
#include <cuda_runtime.h>
#include <cuda_bf16.h>
#include <math.h>
#include <stddef.h>

#define BATCH  64
#define NTOK   4096
#define DIM    256
#define SDIM   256
#define KSLOT  8
#define EPSA   1e-8f
#define LNEPS  1e-5f
#define NROWS  (BATCH*NTOK)       /* 262144 */
#define NCHUNK 8                  /* 512 tokens per chunk */

/* ------------- scratch (device globals; no allocation allowed) ---------- */
__device__ __align__(16) __nv_bfloat16 g_Ah[(size_t)NROWS*DIM];    /* 128 MB */
__device__ __align__(16) __nv_bfloat16 g_WkT[256*256];  /* WkT[d][s]=Wk[s,d]*g[d]/16 */
__device__ __align__(16) __nv_bfloat16 g_Wvf[256*256];  /* Wvf[s][d]=Wv[s,d]*g[d]   */
__device__ __align__(16) float g_cbk[256];
__device__ __align__(16) float g_cbv[256];
__device__ __align__(16) float g_slots[BATCH*KSLOT*SDIM];
__device__ __align__(16) __nv_bfloat16 g_qkb[BATCH*KSLOT*DIM];
__device__ __align__(16) float g_qk0[BATCH*KSLOT];
__device__ __align__(16) float g_updpart[NCHUNK*BATCH*KSLOT*DIM];  /* 4 MB */
__device__ __align__(16) float g_cspart[BATCH*NCHUNK*KSLOT];

__device__ __forceinline__ float sigmoidf_(float x){ return 1.0f/(1.0f + expf(-x)); }
__device__ __forceinline__ float dot4_(float4 a, float4 b){
    return a.x*b.x + a.y*b.y + a.z*b.z + a.w*b.w;
}

/* ----------------------- PTX helpers ----------------------------------- */
__device__ __forceinline__ unsigned smem_u32(const void* p){
    return (unsigned)__cvta_generic_to_shared(p);
}
__device__ __forceinline__ void cp16(unsigned dst, const void* src){
    asm volatile("cp.async.cg.shared.global [%0],[%1],16;\n"::"r"(dst),"l"(src));
}
__device__ __forceinline__ void cp_commit(){ asm volatile("cp.async.commit_group;\n"::); }
__device__ __forceinline__ void cp_wait1(){ asm volatile("cp.async.wait_group 1;\n"::); }
__device__ __forceinline__ void cp_wait0(){ asm volatile("cp.async.wait_group 0;\n"::); }
__device__ __forceinline__ void ldm4(unsigned&r0,unsigned&r1,unsigned&r2,unsigned&r3,unsigned a){
    asm volatile("ldmatrix.sync.aligned.m8n8.x4.shared.b16 {%0,%1,%2,%3},[%4];\n"
        :"=r"(r0),"=r"(r1),"=r"(r2),"=r"(r3):"r"(a));
}
__device__ __forceinline__ void ldm4t(unsigned&r0,unsigned&r1,unsigned&r2,unsigned&r3,unsigned a){
    asm volatile("ldmatrix.sync.aligned.m8n8.x4.trans.shared.b16 {%0,%1,%2,%3},[%4];\n"
        :"=r"(r0),"=r"(r1),"=r"(r2),"=r"(r3):"r"(a));
}
__device__ __forceinline__ void mma16816(float* c, const unsigned* a, unsigned b0, unsigned b1){
    asm volatile("mma.sync.aligned.m16n8k16.row.col.f32.bf16.bf16.f32 "
        "{%0,%1,%2,%3},{%4,%5,%6,%7},{%8,%9},{%0,%1,%2,%3};\n"
        :"+f"(c[0]),"+f"(c[1]),"+f"(c[2]),"+f"(c[3])
        :"r"(a[0]),"r"(a[1]),"r"(a[2]),"r"(a[3]),"r"(b0),"r"(b1));
}

/* ---------------------- 1. slots = mu + exp(ls)*noise ------------------- */
__global__ void k_init_slots(const float* __restrict__ noise,
                             const float* __restrict__ mu,
                             const float* __restrict__ lsig){
    int i = blockIdx.x*256 + threadIdx.x;
    int s = i & (SDIM-1);
    g_slots[i] = mu[s] + expf(lsig[s]) * noise[i];
}

/* ------------- 2. LN(inputs, no affine) -> bf16 ------------------------ */
__global__ __launch_bounds__(256) void k_prep_a(const float* __restrict__ inp){
    int row  = blockIdx.x*8 + (threadIdx.x >> 5);
    int lane = threadIdx.x & 31;
    const float4* p = (const float4*)(inp + (size_t)row*DIM);
    float4 a = p[lane*2], b = p[lane*2+1];
    float x[8] = {a.x,a.y,a.z,a.w,b.x,b.y,b.z,b.w};
    float s = 0.f, q = 0.f;
#pragma unroll
    for (int i=0;i<8;i++){ s += x[i]; q += x[i]*x[i]; }
#pragma unroll
    for (int o=16;o;o>>=1){
        s += __shfl_xor_sync(0xffffffffu, s, o);
        q += __shfl_xor_sync(0xffffffffu, q, o);
    }
    float m = s*(1.0f/DIM);
    float rstd = rsqrtf(q*(1.0f/DIM) - m*m + LNEPS);
    __nv_bfloat162 h2[4];
#pragma unroll
    for (int i=0;i<4;i++){
        h2[i] = __halves2bfloat162(__float2bfloat16((x[2*i]-m)*rstd),
                                   __float2bfloat16((x[2*i+1]-m)*rstd));
    }
    size_t off = (size_t)row*DIM + lane*8;
    *(uint4*)(g_Ah + off) = *(uint4*)h2;
}

/* ------------- 3. weight prep: fold gamma/beta/scale -------------------- */
__global__ __launch_bounds__(256) void k_prep_w(const float* __restrict__ Wk,
        const float* __restrict__ Wv, const float* __restrict__ gin,
        const float* __restrict__ bin){
    __shared__ float rk[8], rv[8];
    int s = blockIdx.x, d = threadIdx.x;
    int w = d>>5, l = d&31;
    float gk = gin[d], bt = bin[d];
    float wk = Wk[s*256+d], wv = Wv[s*256+d];
    g_WkT[d*256+s] = __float2bfloat16(wk*gk*0.0625f);
    g_Wvf[s*256+d] = __float2bfloat16(wv*gk);
    float pk = wk*bt, pv = wv*bt;
#pragma unroll
    for (int o=16;o;o>>=1){
        pk += __shfl_xor_sync(0xffffffffu, pk, o);
        pv += __shfl_xor_sync(0xffffffffu, pv, o);
    }
    if (l==0){ rk[w]=pk; rv[w]=pv; }
    __syncthreads();
    if (d==0){
        float sk=0.f, sv=0.f;
#pragma unroll
        for (int i=0;i<8;i++){ sk+=rk[i]; sv+=rv[i]; }
        g_cbk[s] = sk*0.0625f;
        g_cbv[s] = sv;
    }
}

/* ------------- 4. q = LN(slots)@Wq^T ; qk = q@Wkf ; qk0 ----------------- */
/* grid 64 (batch), 512 threads: half = tid>>8 handles 4 slots             */
__global__ __launch_bounds__(512) void k_qk(const float* __restrict__ Wq,
        const float* __restrict__ gsl, const float* __restrict__ bsl){
    __shared__ float xs[8][256];
    __shared__ float qs[8][256];
    __shared__ float redp[16][4];
    int b = blockIdx.x, tid = threadIdx.x;
    int t = tid & 255, half = tid >> 8;
    int w = tid>>5, l = tid&31;
    /* LN of slot row w (warps 0-7 only) */
    if (w < 8){
        const float4* sr = (const float4*)(g_slots + (b*8+w)*256);
        float4 a = sr[l*2], c = sr[l*2+1];
        float v[8] = {a.x,a.y,a.z,a.w,c.x,c.y,c.z,c.w};
        float s=0.f, q=0.f;
#pragma unroll
        for (int i=0;i<8;i++){ s+=v[i]; q+=v[i]*v[i]; }
#pragma unroll
        for (int o=16;o;o>>=1){
            s += __shfl_xor_sync(0xffffffffu, s, o);
            q += __shfl_xor_sync(0xffffffffu, q, o);
        }
        float m = s*(1.0f/256.f);
        float rstd = rsqrtf(q*(1.0f/256.f)-m*m+LNEPS);
#pragma unroll
        for (int i=0;i<8;i++)
            xs[w][l*8+i] = (v[i]-m)*rstd*gsl[l*8+i] + bsl[l*8+i];
    }
    __syncthreads();
    /* q[half*4+k][t] */
    float q4[4] = {0,0,0,0};
    {
        const float4* wq = (const float4*)(Wq + (size_t)t*256);
#pragma unroll 8
        for (int d4=0; d4<64; d4++){
            float4 wv4 = wq[d4];
#pragma unroll
            for (int k=0;k<4;k++)
                q4[k] += dot4_(wv4, *(const float4*)&xs[half*4+k][d4*4]);
        }
    }
    /* qk0 partials */
    {
        float cbt = g_cbk[t];
        float p[4];
#pragma unroll
        for (int k=0;k<4;k++) p[k] = q4[k]*cbt;
#pragma unroll
        for (int k=0;k<4;k++)
#pragma unroll
            for (int o=16;o;o>>=1) p[k] += __shfl_xor_sync(0xffffffffu, p[k], o);
        if (l==0)
#pragma unroll
            for (int k=0;k<4;k++) redp[w][k] = p[k];
    }
#pragma unroll
    for (int k=0;k<4;k++) qs[half*4+k][t] = q4[k];
    __syncthreads();
    if (tid<8){
        float s=0.f;
        int w0 = (tid>>2)*8;
#pragma unroll
        for (int i=0;i<8;i++) s += redp[w0+i][tid&3];
        g_qk0[b*8+tid] = s;
    }
    /* qk[half*4+k][d=t] = sum_s qs[..][s]*WkT[t][s] */
    float o4[4] = {0,0,0,0};
    {
        const uint4* wkt = (const uint4*)(g_WkT + (size_t)t*256);
#pragma unroll 4
        for (int s8=0; s8<32; s8++){
            uint4 raw = wkt[s8];
            const __nv_bfloat162* p2 = (const __nv_bfloat162*)&raw;
#pragma unroll
            for (int j2=0;j2<4;j2++){
                float2 f = __bfloat1622float2(p2[j2]);
#pragma unroll
                for (int k=0;k<4;k++){
                    o4[k] += qs[half*4+k][s8*8+2*j2]  *f.x;
                    o4[k] += qs[half*4+k][s8*8+2*j2+1]*f.y;
                }
            }
        }
    }
#pragma unroll
    for (int k=0;k<4;k++)
        g_qkb[(b*8+half*4+k)*256 + t] = __float2bfloat16(o4[k]);
}

/* ------------- 5. fused: logits(MMA) + softmax + ux(MMA, via trans) ----- */
/* grid (8 chunks, 64 batches), 256 thr, 512 tokens/block, 4 subtiles x128 */
#define LDSB2 264                        /* bf16 elems per padded row */
#define XTB   (128*LDSB2*2)              /* 67584 B per x' buffer */
#define ATT_OFF (2*XTB)                  /* attn_t[8][136] bf16 */
#define CS_OFF  (ATT_OFF + 2176)
#define QK0_OFF (CS_OFF + 256)
#define SMEMB   (QK0_OFF + 64)
__global__ __launch_bounds__(256) void k_fused(){
    extern __shared__ __align__(16) char sm[];
    __nv_bfloat16* attn_t = (__nv_bfloat16*)(sm + ATT_OFF);  /* [8][136] */
    float* csum_s = (float*)(sm + CS_OFF);                   /* [8 warps][8] */
    float* qk0s   = (float*)(sm + QK0_OFF);
    const unsigned sb = smem_u32(sm);
    const int b = blockIdx.y, chunk = blockIdx.x;
    const int t = threadIdx.x, w = t>>5, l = t&31;
    const int col0 = (l&3)*2;

    /* B fragments: qk for this batch, resident in registers */
    unsigned bf[16][2];
    {
        const __nv_bfloat16* qkb = g_qkb + ((size_t)b*8 + (l>>2))*256 + col0;
#pragma unroll
        for (int s16=0;s16<16;s16++){
            bf[s16][0] = *(const unsigned*)(qkb + s16*16);
            bf[s16][1] = *(const unsigned*)(qkb + s16*16 + 8);
        }
    }
    if (t<8) qk0s[t] = g_qk0[b*8+t];

    float cs0=0.f, cs1=0.f;
    float ua[2][4];
#pragma unroll
    for (int i=0;i<2;i++)
#pragma unroll
        for (int j=0;j<4;j++) ua[i][j]=0.f;

    const size_t grow0 = (size_t)(b*NTOK + chunk*512);
    auto load_x = [&](int buf, int tok0){
        unsigned dstb = sb + buf*XTB;
        int rr = t>>1;
        int sg0 = (t&1)*16;
#pragma unroll
        for (int j=0;j<16;j++){
            int seg = sg0 + j;
            cp16(dstb + (unsigned)(rr*528 + seg*16),
                 g_Ah + (grow0 + tok0 + rr)*DIM + seg*8);
        }
    };
    load_x(0, 0); cp_commit();

#pragma unroll 1
    for (int st=0; st<4; st++){
        __syncthreads();                 /* phase2(st-1) done before buffer/attn reuse */
        if (st<3){ load_x((st+1)&1, (st+1)*128); cp_commit(); cp_wait1(); }
        else cp_wait0();
        __syncthreads();
        unsigned xb = sb + (st&1)*XTB;
        /* phase 1: warp w -> tokens [w*16, w*16+16), logits via MMA */
        float cacc[4] = {0.f,0.f,0.f,0.f};
#pragma unroll
        for (int s16=0;s16<16;s16++){
            unsigned a[4];
            unsigned addr = xb + (unsigned)(((w*16 + (l&15))*LDSB2
                               + s16*16 + ((l>>4)<<3))*2);
            ldm4(a[0],a[1],a[2],a[3], addr);
            mma16816(cacc, a, bf[s16][0], bf[s16][1]);
        }
        cacc[0] += qk0s[col0]; cacc[1] += qk0s[col0+1];
        cacc[2] += qk0s[col0]; cacc[3] += qk0s[col0+1];
        /* softmax over 8 slots via quad shuffles */
        float m0 = fmaxf(cacc[0],cacc[1]), m1 = fmaxf(cacc[2],cacc[3]);
        m0 = fmaxf(m0, __shfl_xor_sync(0xffffffffu, m0, 1));
        m1 = fmaxf(m1, __shfl_xor_sync(0xffffffffu, m1, 1));
        m0 = fmaxf(m0, __shfl_xor_sync(0xffffffffu, m0, 2));
        m1 = fmaxf(m1, __shfl_xor_sync(0xffffffffu, m1, 2));
        float e0 = expf(cacc[0]-m0), e1 = expf(cacc[1]-m0);
        float e2 = expf(cacc[2]-m1), e3 = expf(cacc[3]-m1);
        float s0 = e0+e1, s1 = e2+e3;
        s0 += __shfl_xor_sync(0xffffffffu, s0, 1);
        s1 += __shfl_xor_sync(0xffffffffu, s1, 1);
        s0 += __shfl_xor_sync(0xffffffffu, s0, 2);
        s1 += __shfl_xor_sync(0xffffffffu, s1, 2);
        float i0 = 1.0f/s0, i1 = 1.0f/s1;
        float a0 = e0*i0+EPSA, a1 = e1*i0+EPSA;
        float a2 = e2*i1+EPSA, a3 = e3*i1+EPSA;
        cs0 += a0+a2; cs1 += a1+a3;
        int row = w*16 + (l>>2);
        attn_t[col0*136 + row]           = __float2bfloat16(a0);
        attn_t[(col0+1)*136 + row]       = __float2bfloat16(a1);
        attn_t[col0*136 + row + 8]       = __float2bfloat16(a2);
        attn_t[(col0+1)*136 + row + 8]   = __float2bfloat16(a3);
        __syncthreads();
        /* phase 2: ux += x'^T @ attn ; warp w -> dims [w*32, w*32+32) */
#pragma unroll
        for (int kt=0; kt<8; kt++){
            unsigned b0 = *(const unsigned*)&attn_t[(l>>2)*136 + kt*16 + (l&3)*2];
            unsigned b1 = *(const unsigned*)&attn_t[(l>>2)*136 + kt*16 + 8 + (l&3)*2];
            int tok = kt*16 + (l&7) + ((l>>4)<<3);
#pragma unroll
            for (int mt=0; mt<2; mt++){
                int dd = w*32 + mt*16 + ((l>>3)&1)*8;
                unsigned a[4];
                ldm4t(a[0],a[1],a[2],a[3],
                      xb + (unsigned)((tok*LDSB2 + dd)*2));
                mma16816(ua[mt], a, b0, b1);
            }
        }
    }
    /* colsum reduction (lanes sharing l&3 across rows) */
    cs0 += __shfl_xor_sync(0xffffffffu, cs0, 4);
    cs1 += __shfl_xor_sync(0xffffffffu, cs1, 4);
    cs0 += __shfl_xor_sync(0xffffffffu, cs0, 8);
    cs1 += __shfl_xor_sync(0xffffffffu, cs1, 8);
    cs0 += __shfl_xor_sync(0xffffffffu, cs0, 16);
    cs1 += __shfl_xor_sync(0xffffffffu, cs1, 16);
    if (l<4){ csum_s[w*8 + col0] = cs0; csum_s[w*8 + col0 + 1] = cs1; }
    __syncthreads();
    if (t<8){
        float s=0.f;
#pragma unroll
        for (int ww=0;ww<8;ww++) s += csum_s[ww*8+t];
        g_cspart[(b*NCHUNK + chunk)*KSLOT + t] = s;
    }
    /* write ux fragments: C rows = dims, cols = slots */
    {
        size_t base = ((size_t)chunk*BATCH*KSLOT) + b*8;
        int s0 = (l&3)*2;
#pragma unroll
        for (int mt=0;mt<2;mt++){
            int d0 = w*32 + mt*16 + (l>>2);
            g_updpart[(base + s0  )*256 + d0]     = ua[mt][0];
            g_updpart[(base + s0+1)*256 + d0]     = ua[mt][1];
            g_updpart[(base + s0  )*256 + d0 + 8] = ua[mt][2];
            g_updpart[(base + s0+1)*256 + d0 + 8] = ua[mt][3];
        }
    }
}

/* ------------- 6. finalize updates + GRU + optional MLP ----------------- */
__global__ __launch_bounds__(256) void k_gru(
        const float* __restrict__ Wih, const float* __restrict__ Whh,
        const float* __restrict__ bih, const float* __restrict__ bhh,
        const float* __restrict__ W1,  const float* __restrict__ b1,
        const float* __restrict__ W2,  const float* __restrict__ b2,
        const float* __restrict__ gm,  const float* __restrict__ bm,
        int do_mlp, float* __restrict__ out){
    int t = threadIdx.x;
    int r0 = blockIdx.x * 4;
    __shared__ float Us[4][256];
    __shared__ float Xs[4][256];
    __shared__ float Hs[4][256];
    __shared__ float Hm[4][512];
    __shared__ float mred[4][2];
    __shared__ float csum[4];
#pragma unroll
    for (int r=0;r<4;r++){
        int gr = r0+r;
        float s=0.f;
#pragma unroll
        for (int cc=0;cc<NCHUNK;cc++)
            s += g_updpart[(((size_t)cc*BATCH*KSLOT) + gr)*256 + t];
        Us[r][t] = s;
        Hs[r][t] = g_slots[gr*256 + t];
    }
    if (t<4){
        int gr = r0+t, bb = gr>>3, kk = gr&7;
        float cs=0.f;
#pragma unroll
        for (int cc=0;cc<NCHUNK;cc++) cs += g_cspart[(bb*NCHUNK+cc)*KSLOT + kk];
        csum[t] = cs;
    }
    __syncthreads();
    {
        float acc[4] = {0,0,0,0};
        const uint4* wv = (const uint4*)(g_Wvf + (size_t)t*256);
#pragma unroll 4
        for (int s8=0;s8<32;s8++){
            uint4 raw = wv[s8];
            const __nv_bfloat162* p2 = (const __nv_bfloat162*)&raw;
#pragma unroll
            for (int j2=0;j2<4;j2++){
                float2 f = __bfloat1622float2(p2[j2]);
#pragma unroll
                for (int r=0;r<4;r++){
                    acc[r] += Us[r][s8*8+2*j2]  *f.x;
                    acc[r] += Us[r][s8*8+2*j2+1]*f.y;
                }
            }
        }
        float cbt = g_cbv[t];
#pragma unroll
        for (int r=0;r<4;r++) Xs[r][t] = acc[r]/csum[r] + cbt;
    }
    __syncthreads();

    float gi_[3][4], gh_[3][4];
#pragma unroll
    for (int g=0; g<3; g++){
        float ai[4]={0,0,0,0}, ah[4]={0,0,0,0};
        const float4* wi = (const float4*)(Wih + ((size_t)((g<<8)+t))*256);
        const float4* wh = (const float4*)(Whh + ((size_t)((g<<8)+t))*256);
#pragma unroll 4
        for (int d=0; d<64; d++){
            float4 a = wi[d], cc = wh[d];
#pragma unroll
            for (int r=0;r<4;r++){
                float4 xv = *(const float4*)&Xs[r][d<<2];
                float4 hv = *(const float4*)&Hs[r][d<<2];
                ai[r] += a.x*xv.x + a.y*xv.y + a.z*xv.z + a.w*xv.w;
                ah[r] += cc.x*hv.x + cc.y*hv.y + cc.z*hv.z + cc.w*hv.w;
            }
        }
        float bi = bih[(g<<8)+t], bh = bhh[(g<<8)+t];
#pragma unroll
        for (int r=0;r<4;r++){ gi_[g][r] = ai[r]+bi; gh_[g][r] = ah[r]+bh; }
    }
    __syncthreads();

    float newv[4];
#pragma unroll
    for (int r=0;r<4;r++){
        float hh = Hs[r][t];
        float rr = sigmoidf_(gi_[0][r] + gh_[0][r]);
        float zz = sigmoidf_(gi_[1][r] + gh_[1][r]);
        float nn = tanhf(gi_[2][r] + rr*gh_[2][r]);
        newv[r] = (1.0f - zz)*nn + zz*hh;
    }
#pragma unroll
    for (int r=0;r<4;r++) Xs[r][t] = newv[r];

    if (!do_mlp){
#pragma unroll
        for (int r=0;r<4;r++){
            g_slots[(r0+r)*256 + t] = newv[r];
            if (out) out[(r0+r)*256 + t] = newv[r];
        }
        return;
    }
    __syncthreads();
    int warp = t>>5, lane = t&31;
    if (warp < 4){
        float s=0.f, q=0.f;
#pragma unroll
        for (int j=0;j<8;j++){
            float xv = Xs[warp][lane + (j<<5)];
            s += xv; q += xv*xv;
        }
#pragma unroll
        for (int o=16;o;o>>=1){
            s += __shfl_xor_sync(0xffffffffu, s, o);
            q += __shfl_xor_sync(0xffffffffu, q, o);
        }
        if (lane==0){
            float m = s*(1.0f/256.f);
            mred[warp][0] = m;
            mred[warp][1] = rsqrtf(q*(1.0f/256.f) - m*m + LNEPS);
        }
    }
    __syncthreads();
    float gmt = gm[t], bmt = bm[t];
#pragma unroll
    for (int r=0;r<4;r++)
        Hs[r][t] = (Xs[r][t] - mred[r][0])*mred[r][1]*gmt + bmt;
    __syncthreads();
#pragma unroll
    for (int hblk=0; hblk<2; hblk++){
        int ho = t + (hblk<<8);
        float acc[4]={0,0,0,0};
        const float4* wp = (const float4*)(W1 + (size_t)ho*256);
#pragma unroll 4
        for (int d=0; d<64; d++){
            float4 a = wp[d];
#pragma unroll
            for (int r=0;r<4;r++)
                acc[r] += dot4_(a, *(const float4*)&Hs[r][d<<2]);
        }
        float bb = b1[ho];
#pragma unroll
        for (int r=0;r<4;r++) Hm[r][ho] = fmaxf(acc[r]+bb, 0.f);
    }
    __syncthreads();
    {
        float acc[4]={0,0,0,0};
        const float4* wp = (const float4*)(W2 + (size_t)t*512);
#pragma unroll 4
        for (int j=0; j<128; j++){
            float4 a = wp[j];
#pragma unroll
            for (int r=0;r<4;r++)
                acc[r] += dot4_(a, *(const float4*)&Hm[r][j<<2]);
        }
        float bb = b2[t];
#pragma unroll
        for (int r=0;r<4;r++)
            g_slots[(r0+r)*256 + t] = Xs[r][t] + acc[r] + bb;
    }
}

/* ----------------------------- launcher -------------------------------- */
extern "C" void kernel_launch(void* const* d_in, const int* in_sizes, int n_in,
                              void* d_out, int out_size){
    (void)in_sizes; (void)n_in; (void)out_size;
    const float* inputs = (const float*)d_in[0];
    const float* noise  = (const float*)d_in[1];
    const float* mu     = (const float*)d_in[2];
    const float* lsig   = (const float*)d_in[3];
    const float* gin    = (const float*)d_in[4];
    const float* bin    = (const float*)d_in[5];
    const float* gsl    = (const float*)d_in[6];
    const float* bsl    = (const float*)d_in[7];
    const float* gm     = (const float*)d_in[8];
    const float* bm     = (const float*)d_in[9];
    const float* Wq     = (const float*)d_in[10];
    const float* Wk     = (const float*)d_in[11];
    const float* Wv     = (const float*)d_in[12];
    const float* Wih    = (const float*)d_in[13];
    const float* Whh    = (const float*)d_in[14];
    const float* bih    = (const float*)d_in[15];
    const float* bhh    = (const float*)d_in[16];
    const float* W1     = (const float*)d_in[17];
    const float* b1     = (const float*)d_in[18];
    const float* W2     = (const float*)d_in[19];
    const float* b2     = (const float*)d_in[20];
    float* out = (float*)d_out;

    cudaFuncSetAttribute(k_fused,
                         cudaFuncAttributeMaxDynamicSharedMemorySize, SMEMB);

    k_init_slots<<<512, 256>>>(noise, mu, lsig);
    k_prep_a<<<NROWS/8, 256>>>(inputs);
    k_prep_w<<<256, 256>>>(Wk, Wv, gin, bin);
    for (int it=0; it<3; it++){
        k_qk<<<BATCH, 512>>>(Wq, gsl, bsl);
        k_fused<<<dim3(NCHUNK, BATCH), 256, SMEMB>>>();
        k_gru<<<128, 256>>>(Wih, Whh, bih, bhh, W1, b1, W2, b2, gm, bm,
                            (it < 2) ? 1 : 0, (it == 2) ? out : nullptr);
    }
}